// round 8
// baseline (speedup 1.0000x reference)
#include <cuda_runtime.h>
#include <cuda_bf16.h>
#include <math.h>
#include <stdint.h>

#define NN   50000
#define NNP  50048              // padded to multiple of 128
#define EE   400000
#define GGR  500
#define FIN  92
#define DH   256
#define DEMB 128
#define EPSLN 1e-5f

// ---------------- scratch (no allocations allowed) ----------------
__device__ float g_xw[NN * DH];            // GEMM fp32 output (pre-aggregation)
__device__ float g_dinv[NN];
__device__ int   g_deg[NN];
__device__ int   g_off[NN];
__device__ int   g_cur[NN];
__device__ int   g_csr[EE];
__device__ int   g_bsum[256];
__device__ float g_hg[GGR * DEMB];

// bf16 hi/lo split operand buffers (pad regions stay zero: zero-init, never written)
__device__ __nv_bfloat16 g_xA_hi[NNP * 128];
__device__ __nv_bfloat16 g_xA_lo[NNP * 128];
__device__ __nv_bfloat16 g_h1_hi[NNP * 256];
__device__ __nv_bfloat16 g_h1_lo[NNP * 256];
__device__ __nv_bfloat16 g_h2_hi[NNP * 256];
__device__ __nv_bfloat16 g_h2_lo[NNP * 256];
__device__ __nv_bfloat16 g_w1_hi[256 * 128], g_w1_lo[256 * 128];  // nfcW^T padded
__device__ __nv_bfloat16 g_w2_hi[256 * 256], g_w2_lo[256 * 256];  // gc1W^T
__device__ __nv_bfloat16 g_w3_hi[128 * 256], g_w3_lo[128 * 256];  // gc2W^T

// ---------------- small helpers ----------------
__device__ __forceinline__ float warp_sum(float v) {
#pragma unroll
    for (int o = 16; o > 0; o >>= 1) v += __shfl_xor_sync(0xffffffffu, v, o);
    return v;
}
__device__ __forceinline__ float lrelu(float v) { return v > 0.f ? v : 0.01f * v; }

__device__ __forceinline__ void red_add_v4(float* p, float4 v) {
    asm volatile("red.global.add.v4.f32 [%0], {%1, %2, %3, %4};"
                 :: "l"(p), "f"(v.x), "f"(v.y), "f"(v.z), "f"(v.w) : "memory");
}
__device__ __forceinline__ uint32_t pack_bf16(float a, float b) {
    __nv_bfloat162 t(__float2bfloat16(a), __float2bfloat16(b));
    return *reinterpret_cast<uint32_t*>(&t);
}
__device__ __forceinline__ uint32_t smem_u32(const void* p) {
    return (uint32_t)__cvta_generic_to_shared(p);
}
__device__ __forceinline__ void ldsm_x4(uint32_t& r0, uint32_t& r1, uint32_t& r2,
                                        uint32_t& r3, uint32_t addr) {
    asm volatile("ldmatrix.sync.aligned.m8n8.x4.shared.b16 {%0,%1,%2,%3}, [%4];"
                 : "=r"(r0), "=r"(r1), "=r"(r2), "=r"(r3) : "r"(addr));
}
__device__ __forceinline__ void mma16816(float* d, const uint32_t* a, const uint32_t* b) {
    asm volatile(
        "mma.sync.aligned.m16n8k16.row.col.f32.bf16.bf16.f32 "
        "{%0,%1,%2,%3}, {%4,%5,%6,%7}, {%8,%9}, {%0,%1,%2,%3};"
        : "+f"(d[0]), "+f"(d[1]), "+f"(d[2]), "+f"(d[3])
        : "r"(a[0]), "r"(a[1]), "r"(a[2]), "r"(a[3]), "r"(b[0]), "r"(b[1]));
}
__device__ __forceinline__ void cpasync16(uint32_t saddr, const void* g) {
    asm volatile("cp.async.cg.shared.global [%0], [%1], 16;" :: "r"(saddr), "l"(g));
}

// ---------------- degree / zero / CSR ----------------
__global__ void k_zero() {
    int i = blockIdx.x * blockDim.x + threadIdx.x;
    if (i < NN) g_deg[i] = 0;
    if (i < GGR * DEMB) g_hg[i] = 0.f;
}
__global__ void k_deg_count(const int* __restrict__ ei) {
    int e = blockIdx.x * blockDim.x + threadIdx.x;
    if (e < EE) atomicAdd(&g_deg[ei[EE + e]], 1);
}
// scan pass 1: block-local exclusive scan of deg; also computes dinv.
__global__ __launch_bounds__(256) void k_scan1() {
    __shared__ int ws[8];
    int i = blockIdx.x * 256 + threadIdx.x;
    int lane = threadIdx.x & 31, w = threadIdx.x >> 5;
    int v = (i < NN) ? g_deg[i] : 0;
    if (i < NN) g_dinv[i] = rsqrtf((float)v + 1.0f);
    int x = v;
#pragma unroll
    for (int o = 1; o < 32; o <<= 1) {
        int t = __shfl_up_sync(0xffffffffu, x, o);
        if (lane >= o) x += t;
    }
    if (lane == 31) ws[w] = x;
    __syncthreads();
    if (w == 0 && lane < 8) {
        int y = ws[lane];
#pragma unroll
        for (int o = 1; o < 8; o <<= 1) {
            int t = __shfl_up_sync(0xffu, y, o);
            if (lane >= o) y += t;
        }
        ws[lane] = y;
    }
    __syncthreads();
    int base = (w > 0) ? ws[w - 1] : 0;
    if (i < NN) g_off[i] = base + x - v;
    if (threadIdx.x == 255) g_bsum[blockIdx.x] = ws[7];
}
__global__ __launch_bounds__(256) void k_scan2(int nblk) {
    __shared__ int ws[8];
    int lane = threadIdx.x & 31, w = threadIdx.x >> 5;
    int v = (threadIdx.x < nblk) ? g_bsum[threadIdx.x] : 0;
    int x = v;
#pragma unroll
    for (int o = 1; o < 32; o <<= 1) {
        int t = __shfl_up_sync(0xffffffffu, x, o);
        if (lane >= o) x += t;
    }
    if (lane == 31) ws[w] = x;
    __syncthreads();
    if (w == 0 && lane < 8) {
        int y = ws[lane];
#pragma unroll
        for (int o = 1; o < 8; o <<= 1) {
            int t = __shfl_up_sync(0xffu, y, o);
            if (lane >= o) y += t;
        }
        ws[lane] = y;
    }
    __syncthreads();
    int base = (w > 0) ? ws[w - 1] : 0;
    if (threadIdx.x < nblk) g_bsum[threadIdx.x] = base + x - v;
}
__global__ void k_scan3() {
    int i = blockIdx.x * blockDim.x + threadIdx.x;
    if (i < NN) {
        int o = g_off[i] + g_bsum[i >> 8];
        g_off[i] = o;
        g_cur[i] = o;
    }
}
__global__ void k_fill(const int* __restrict__ ei) {
    int e = blockIdx.x * blockDim.x + threadIdx.x;
    if (e < EE) {
        int s = ei[e], d = ei[EE + e];
        int pos = atomicAdd(&g_cur[d], 1);
        g_csr[pos] = s;
    }
}

// ---------------- fused conversions: x + 3 weights, one launch ----------------
#define W1SZ (256 * 128)
#define W2SZ (256 * 256)
#define W3SZ (128 * 256)
#define XSZ  (NN * 128)
__global__ void k_cvt_all(const float* __restrict__ x, const float* __restrict__ W1,
                          const float* __restrict__ W2, const float* __restrict__ W3)
{
    int idx = blockIdx.x * blockDim.x + threadIdx.x;
    float v;
    __nv_bfloat16 *oh, *ol;
    int o;
    if (idx < XSZ) {
        int row = idx >> 7, col = idx & 127;
        v = (col < FIN) ? x[row * FIN + col] : 0.f;
        oh = g_xA_hi; ol = g_xA_lo; o = idx;
    } else if (idx < XSZ + W1SZ) {
        o = idx - XSZ;                      // [N=256][KP=128], K=92
        int n = o >> 7, k = o & 127;
        v = (k < FIN) ? W1[k * DH + n] : 0.f;
        oh = g_w1_hi; ol = g_w1_lo;
    } else if (idx < XSZ + W1SZ + W2SZ) {
        o = idx - XSZ - W1SZ;               // [N=256][KP=256], K=256
        int n = o >> 8, k = o & 255;
        v = W2[k * DH + n];
        oh = g_w2_hi; ol = g_w2_lo;
    } else if (idx < XSZ + W1SZ + W2SZ + W3SZ) {
        o = idx - XSZ - W1SZ - W2SZ;        // [N=128][KP=256], K=256
        int n = o >> 8, k = o & 255;
        v = W3[k * DEMB + n];
        oh = g_w3_hi; ol = g_w3_lo;
    } else return;
    float h = __bfloat162float(__float2bfloat16(v));
    oh[o] = __float2bfloat16(v);
    ol[o] = __float2bfloat16(v - h);
}

// ---------------- mma.sync bf16x3 GEMM, cp.async double-buffered ----------------
// C[128 x 128] tile per CTA.  D = Ah*Bh^T + Ah*Bl^T + Al*Bh^T, fp32 accum in regs.
#define SM_AH 0
#define SM_AL 16384
#define SM_BH 32768
#define SM_BL 49152
#define BUFSZ 65536
#define SMEM_BYTES (2 * BUFSZ)

template <int KP, int EPI>
__global__ __launch_bounds__(256) void k_mma(
    const __nv_bfloat16* __restrict__ Ah, const __nv_bfloat16* __restrict__ Al,
    const __nv_bfloat16* __restrict__ Bh, const __nv_bfloat16* __restrict__ Bl,
    const float* __restrict__ bias, float* __restrict__ C,
    __nv_bfloat16* __restrict__ Ohi, __nv_bfloat16* __restrict__ Olo, int Nfull)
{
    extern __shared__ __align__(128) char smem[];
    const uint32_t sb = smem_u32(smem);
    const int tid = threadIdx.x, wid = tid >> 5, lid = tid & 31;
    const int bm = blockIdx.y * 128;
    const int bn = blockIdx.x * 128;
    const int warp_m = wid & 3;
    const int warp_n = wid >> 2;

    float acc[2][8][4];
#pragma unroll
    for (int mt = 0; mt < 2; mt++)
#pragma unroll
        for (int nt = 0; nt < 8; nt++)
#pragma unroll
            for (int q = 0; q < 4; q++) acc[mt][nt][q] = 0.f;

    const int a_r = (lid & 7) + ((lid >> 3) & 1) * 8;
    const int a_u = (lid >> 4) & 1;
    const int b_r = (lid & 7) + ((lid >> 4) & 1) * 8;
    const int b_u = (lid >> 3) & 1;

    constexpr int NKC = KP / 64;

    // prefetch: chunk kc into buffer set `buf`
    auto prefetch = [&](int kc, int buf) {
        uint32_t base = sb + buf * BUFSZ;
#pragma unroll
        for (int i = 0; i < 4; i++) {
            int idx = tid + i * 256;
            int r = idx >> 3, c16 = idx & 7;
            uint32_t so = (uint32_t)(r * 128 + ((c16 ^ (r & 7)) * 16));
            size_t ga = (size_t)(bm + r) * KP + kc * 64 + c16 * 8;
            size_t gb = (size_t)(bn + r) * KP + kc * 64 + c16 * 8;
            cpasync16(base + SM_AH + so, Ah + ga);
            cpasync16(base + SM_AL + so, Al + ga);
            cpasync16(base + SM_BH + so, Bh + gb);
            cpasync16(base + SM_BL + so, Bl + gb);
        }
        asm volatile("cp.async.commit_group;" ::: "memory");
    };

    prefetch(0, 0);
    for (int kc = 0; kc < NKC; kc++) {
        if (kc + 1 < NKC) {
            prefetch(kc + 1, (kc + 1) & 1);
            asm volatile("cp.async.wait_group 1;" ::: "memory");
        } else {
            asm volatile("cp.async.wait_group 0;" ::: "memory");
        }
        __syncthreads();
        const uint32_t base = sb + (kc & 1) * BUFSZ;

#pragma unroll
        for (int k16 = 0; k16 < 4; k16++) {
            uint32_t ah[2][4], al[2][4];
#pragma unroll
            for (int mt = 0; mt < 2; mt++) {
                int row = warp_m * 32 + mt * 16 + a_r;
                int u = k16 * 2 + a_u;
                uint32_t off = (uint32_t)(row * 128 + ((u ^ (row & 7)) * 16));
                ldsm_x4(ah[mt][0], ah[mt][1], ah[mt][2], ah[mt][3], base + SM_AH + off);
                ldsm_x4(al[mt][0], al[mt][1], al[mt][2], al[mt][3], base + SM_AL + off);
            }
            uint32_t bh[8][2], bl[8][2];
#pragma unroll
            for (int g = 0; g < 4; g++) {
                int row = warp_n * 64 + g * 16 + b_r;
                int u = k16 * 2 + b_u;
                uint32_t off = (uint32_t)(row * 128 + ((u ^ (row & 7)) * 16));
                ldsm_x4(bh[2 * g][0], bh[2 * g][1], bh[2 * g + 1][0], bh[2 * g + 1][1],
                        base + SM_BH + off);
                ldsm_x4(bl[2 * g][0], bl[2 * g][1], bl[2 * g + 1][0], bl[2 * g + 1][1],
                        base + SM_BL + off);
            }
#pragma unroll
            for (int mt = 0; mt < 2; mt++)
#pragma unroll
                for (int nt = 0; nt < 8; nt++) {
                    mma16816(acc[mt][nt], ah[mt], bh[nt]);
                    mma16816(acc[mt][nt], ah[mt], bl[nt]);
                    mma16816(acc[mt][nt], al[mt], bh[nt]);
                }
        }
        __syncthreads();
    }

    // epilogue straight from accumulator fragments
    const int r_base = bm + warp_m * 32 + (lid >> 2);
    const int c_base = bn + warp_n * 64 + (lid & 3) * 2;
#pragma unroll
    for (int mt = 0; mt < 2; mt++) {
#pragma unroll
        for (int h = 0; h < 2; h++) {
            int row = r_base + mt * 16 + h * 8;
            if (row >= NN) continue;
            if (EPI == 0) {
                float* cp = C + (size_t)row * Nfull;
#pragma unroll
                for (int nt = 0; nt < 8; nt++) {
                    float2 v = make_float2(acc[mt][nt][2 * h], acc[mt][nt][2 * h + 1]);
                    *(float2*)(cp + c_base + nt * 8) = v;
                }
            } else {
#pragma unroll
                for (int nt = 0; nt < 8; nt++) {
                    int col = c_base + nt * 8;
                    float v0 = lrelu(acc[mt][nt][2 * h] + bias[col]);
                    float v1 = lrelu(acc[mt][nt][2 * h + 1] + bias[col + 1]);
                    float h0 = __bfloat162float(__float2bfloat16(v0));
                    float h1 = __bfloat162float(__float2bfloat16(v1));
                    *(uint32_t*)(Ohi + (size_t)row * Nfull + col) = pack_bf16(v0, v1);
                    *(uint32_t*)(Olo + (size_t)row * Nfull + col) = pack_bf16(v0 - h0, v1 - h1);
                }
            }
        }
    }
}

// ---------------- fused aggregate + bias + LN + lrelu (+L2norm +pool / +bf16 emit) ----------------
template <int D, bool L2NORM, bool POOL, bool EMIT>
__global__ __launch_bounds__(256) void k_agg_ln(
    const float* __restrict__ xw, const float* __restrict__ bias,
    const float* __restrict__ gam, const float* __restrict__ bet,
    const int* __restrict__ batch, float* __restrict__ out,
    __nv_bfloat16* __restrict__ Ohi, __nv_bfloat16* __restrict__ Olo)
{
    int row = (blockIdx.x * blockDim.x + threadIdx.x) >> 5;
    int lane = threadIdx.x & 31;
    if (row >= NN) return;
    constexpr int P4 = D / 128;
    const float4* xw4 = (const float4*)xw;
    float di = g_dinv[row];

    float4 acc[P4];
    {
        float s = di * di;
        size_t rb = (size_t)row * (D / 4);
#pragma unroll
        for (int j = 0; j < P4; j++) {
            float4 v = xw4[rb + lane + 32 * j];
            acc[j] = make_float4(v.x * s, v.y * s, v.z * s, v.w * s);
        }
    }
    int o0 = g_off[row];
    int dg = g_deg[row];
    for (int e = 0; e < dg; e++) {
        int s = g_csr[o0 + e];
        float nrm = g_dinv[s] * di;
        size_t sbb = (size_t)s * (D / 4);
#pragma unroll
        for (int j = 0; j < P4; j++) {
            float4 v = xw4[sbb + lane + 32 * j];
            acc[j].x = fmaf(v.x, nrm, acc[j].x);
            acc[j].y = fmaf(v.y, nrm, acc[j].y);
            acc[j].z = fmaf(v.z, nrm, acc[j].z);
            acc[j].w = fmaf(v.w, nrm, acc[j].w);
        }
    }

    const float4* bias4 = (const float4*)bias;
    float s = 0.f;
#pragma unroll
    for (int j = 0; j < P4; j++) {
        float4 bb = bias4[lane + 32 * j];
        acc[j].x += bb.x; acc[j].y += bb.y; acc[j].z += bb.z; acc[j].w += bb.w;
        s += acc[j].x + acc[j].y + acc[j].z + acc[j].w;
    }
    s = warp_sum(s);
    float mu = s * (1.0f / D);
    float q = 0.f;
#pragma unroll
    for (int j = 0; j < P4; j++) {
        float dx = acc[j].x - mu, dy = acc[j].y - mu;
        float dz = acc[j].z - mu, dw = acc[j].w - mu;
        q += dx * dx + dy * dy + dz * dz + dw * dw;
    }
    q = warp_sum(q);
    float r = rsqrtf(q * (1.0f / D) + EPSLN);

    const float4* gam4 = (const float4*)gam;
    const float4* bet4 = (const float4*)bet;
    float ss = 0.f;
#pragma unroll
    for (int j = 0; j < P4; j++) {
        float4 g = gam4[lane + 32 * j];
        float4 b = bet4[lane + 32 * j];
        float4 y;
        y.x = lrelu((acc[j].x - mu) * r * g.x + b.x);
        y.y = lrelu((acc[j].y - mu) * r * g.y + b.y);
        y.z = lrelu((acc[j].z - mu) * r * g.z + b.z);
        y.w = lrelu((acc[j].w - mu) * r * g.w + b.w);
        acc[j] = y;
        ss += y.x * y.x + y.y * y.y + y.z * y.z + y.w * y.w;
    }
    if (L2NORM) {
        ss = warp_sum(ss);
        float inv = 1.0f / fmaxf(sqrtf(ss), 1e-12f);
#pragma unroll
        for (int j = 0; j < P4; j++) {
            acc[j].x *= inv; acc[j].y *= inv; acc[j].z *= inv; acc[j].w *= inv;
        }
    }
    if (EMIT) {
#pragma unroll
        for (int j = 0; j < P4; j++) {
            float4 y = acc[j];
            float hx = __bfloat162float(__float2bfloat16(y.x));
            float hy = __bfloat162float(__float2bfloat16(y.y));
            float hz = __bfloat162float(__float2bfloat16(y.z));
            float hw = __bfloat162float(__float2bfloat16(y.w));
            uint2 vh = make_uint2(pack_bf16(y.x, y.y), pack_bf16(y.z, y.w));
            uint2 vl = make_uint2(pack_bf16(y.x - hx, y.y - hy), pack_bf16(y.z - hz, y.w - hw));
            size_t o = (size_t)row * D + 4 * lane + 128 * j;
            *(uint2*)(Ohi + o) = vh;
            *(uint2*)(Olo + o) = vl;
        }
    } else {
        float4* o4 = (float4*)out + (size_t)row * (D / 4);
#pragma unroll
        for (int j = 0; j < P4; j++) o4[lane + 32 * j] = acc[j];
    }
    if (POOL) {
        int b = batch[row];
#pragma unroll
        for (int j = 0; j < P4; j++)
            red_add_v4(g_hg + (size_t)b * DEMB + (4 * lane + 128 * j), acc[j]);
    }
}

// ---------------- final MLP ----------------
__global__ __launch_bounds__(64) void k_mlp(
    const float* __restrict__ W1, const float* __restrict__ b1,
    const float* __restrict__ W2, const float* __restrict__ b2,
    float* __restrict__ out)
{
    int g = blockIdx.x;
    int t = threadIdx.x;
    __shared__ float sh[DEMB];
    __shared__ float red[2];
    sh[t] = g_hg[(size_t)g * DEMB + t];
    sh[t + 64] = g_hg[(size_t)g * DEMB + 64 + t];
    __syncthreads();
    float s = b1[t];
#pragma unroll
    for (int k = 0; k < DEMB; k++) s = fmaf(sh[k], W1[k * 64 + t], s);
    s = lrelu(s);
    s *= W2[t];
    s = warp_sum(s);
    if ((t & 31) == 0) red[t >> 5] = s;
    __syncthreads();
    if (t == 0) out[g] = red[0] + red[1] + b2[0];
}

// ---------------- launch ----------------
extern "C" void kernel_launch(void* const* d_in, const int* in_sizes, int n_in,
                              void* d_out, int out_size)
{
    const float* x     = (const float*)d_in[0];
    const int*   ei    = (const int*)  d_in[1];
    const int*   batch = (const int*)  d_in[2];
    const float* nfcW  = (const float*)d_in[3];
    const float* nfcb  = (const float*)d_in[4];
    const float* gn1g  = (const float*)d_in[5];
    const float* gn1b  = (const float*)d_in[6];
    const float* gc1W  = (const float*)d_in[7];
    const float* gc1b  = (const float*)d_in[8];
    const float* gn2g  = (const float*)d_in[9];
    const float* gn2b  = (const float*)d_in[10];
    const float* gc2W  = (const float*)d_in[11];
    const float* gc2b  = (const float*)d_in[12];
    const float* fc1W  = (const float*)d_in[13];
    const float* fc1b  = (const float*)d_in[14];
    const float* fc2W  = (const float*)d_in[15];
    const float* fc2b  = (const float*)d_in[16];

    float* out   = (float*)d_out;
    float* outHa = out + GGR;

    float* xw;  cudaGetSymbolAddress((void**)&xw, g_xw);
    __nv_bfloat16 *xAh, *xAl, *h1h, *h1l, *h2h, *h2l;
    __nv_bfloat16 *w1h, *w1l, *w2h, *w2l, *w3h, *w3l;
    cudaGetSymbolAddress((void**)&xAh, g_xA_hi); cudaGetSymbolAddress((void**)&xAl, g_xA_lo);
    cudaGetSymbolAddress((void**)&h1h, g_h1_hi); cudaGetSymbolAddress((void**)&h1l, g_h1_lo);
    cudaGetSymbolAddress((void**)&h2h, g_h2_hi); cudaGetSymbolAddress((void**)&h2l, g_h2_lo);
    cudaGetSymbolAddress((void**)&w1h, g_w1_hi); cudaGetSymbolAddress((void**)&w1l, g_w1_lo);
    cudaGetSymbolAddress((void**)&w2h, g_w2_hi); cudaGetSymbolAddress((void**)&w2l, g_w2_lo);
    cudaGetSymbolAddress((void**)&w3h, g_w3_hi); cudaGetSymbolAddress((void**)&w3l, g_w3_lo);

    cudaFuncSetAttribute(k_mma<128, 1>, cudaFuncAttributeMaxDynamicSharedMemorySize, SMEM_BYTES);
    cudaFuncSetAttribute(k_mma<256, 0>, cudaFuncAttributeMaxDynamicSharedMemorySize, SMEM_BYTES);

    const int NB = (NN + 255) / 256;
    const int MBLK = NNP / 128;  // 391

    // 1) degree + dinv + CSR build
    k_zero<<<(GGR * DEMB + 255) / 256, 256>>>();
    k_deg_count<<<(EE + 255) / 256, 256>>>(ei);
    k_scan1<<<NB, 256>>>();
    k_scan2<<<1, 256>>>(NB);
    k_scan3<<<NB, 256>>>();
    k_fill<<<(EE + 255) / 256, 256>>>(ei);

    // 2) fused operand conversions (x + all 3 weights)
    k_cvt_all<<<(XSZ + W1SZ + W2SZ + W3SZ + 255) / 256, 256>>>(x, nfcW, gc1W, gc2W);

    // 3) encoder: h1 = lrelu(x @ nfcW + b) -> bf16 hi/lo
    k_mma<128, 1><<<dim3(2, MBLK), 256, SMEM_BYTES>>>(
        xAh, xAl, w1h, w1l, nfcb, nullptr, h1h, h1l, DH);

    // 4) conv1: xw = h1 @ gc1W ; agg+LN+lrelu -> h2 bf16 hi/lo
    k_mma<256, 0><<<dim3(2, MBLK), 256, SMEM_BYTES>>>(
        h1h, h1l, w2h, w2l, nullptr, xw, nullptr, nullptr, DH);
    k_agg_ln<DH, false, false, true><<<(NN * 32 + 255) / 256, 256>>>(
        xw, gc1b, gn1g, gn1b, batch, nullptr, h2h, h2l);

    // 5) conv2: xw = h2 @ gc2W ; agg+LN+lrelu+L2norm+pool -> outHa
    k_mma<256, 0><<<dim3(1, MBLK), 256, SMEM_BYTES>>>(
        h2h, h2l, w3h, w3l, nullptr, xw, nullptr, nullptr, DEMB);
    k_agg_ln<DEMB, true, true, false><<<(NN * 32 + 255) / 256, 256>>>(
        xw, gc2b, gn2g, gn2b, batch, outHa, nullptr, nullptr);

    // 6) MLP head
    k_mlp<<<GGR, 64>>>(fc1W, fc1b, fc2W, fc2b, out);
}

// round 11
// speedup vs baseline: 1.2122x; 1.2122x over previous
#include <cuda_runtime.h>
#include <cuda_bf16.h>
#include <math.h>
#include <stdint.h>

#define NN   50000
#define NNP  50048              // padded to multiple of 128
#define EE   400000
#define GGR  500
#define FIN  92
#define DH   256
#define DEMB 128
#define EPSLN 1e-5f

// ---------------- scratch (no allocations allowed) ----------------
__device__ float g_xw[NN * DH];            // GEMM fp32 output (pre-aggregation)
__device__ float g_dinv[NN];
__device__ int   g_deg[NN];
__device__ int   g_off[NN];
__device__ int   g_cur[NN];
__device__ int   g_csr[EE];
__device__ int   g_bsum[256];
__device__ float g_hg[GGR * DEMB];

// bf16 hi/lo split operand buffers (pad regions stay zero: zero-init, never written)
__device__ __nv_bfloat16 g_xA_hi[NNP * 128];
__device__ __nv_bfloat16 g_xA_lo[NNP * 128];
__device__ __nv_bfloat16 g_h1_hi[NNP * 256];
__device__ __nv_bfloat16 g_h1_lo[NNP * 256];
__device__ __nv_bfloat16 g_h2_hi[NNP * 256];
__device__ __nv_bfloat16 g_h2_lo[NNP * 256];
__device__ __nv_bfloat16 g_w1_hi[256 * 128], g_w1_lo[256 * 128];  // nfcW^T padded
__device__ __nv_bfloat16 g_w2_hi[256 * 256], g_w2_lo[256 * 256];  // gc1W^T
__device__ __nv_bfloat16 g_w3_hi[128 * 256], g_w3_lo[128 * 256];  // gc2W^T

// ---------------- small helpers ----------------
__device__ __forceinline__ float warp_sum(float v) {
#pragma unroll
    for (int o = 16; o > 0; o >>= 1) v += __shfl_xor_sync(0xffffffffu, v, o);
    return v;
}
__device__ __forceinline__ float lrelu(float v) { return v > 0.f ? v : 0.01f * v; }

__device__ __forceinline__ void red_add_v4(float* p, float4 v) {
    asm volatile("red.global.add.v4.f32 [%0], {%1, %2, %3, %4};"
                 :: "l"(p), "f"(v.x), "f"(v.y), "f"(v.z), "f"(v.w) : "memory");
}
__device__ __forceinline__ uint32_t pack_bf16(float a, float b) {
    __nv_bfloat162 t(__float2bfloat16(a), __float2bfloat16(b));
    return *reinterpret_cast<uint32_t*>(&t);
}
__device__ __forceinline__ uint32_t smem_u32(const void* p) {
    return (uint32_t)__cvta_generic_to_shared(p);
}
__device__ __forceinline__ void ldsm_x4(uint32_t& r0, uint32_t& r1, uint32_t& r2,
                                        uint32_t& r3, uint32_t addr) {
    asm volatile("ldmatrix.sync.aligned.m8n8.x4.shared.b16 {%0,%1,%2,%3}, [%4];"
                 : "=r"(r0), "=r"(r1), "=r"(r2), "=r"(r3) : "r"(addr));
}
__device__ __forceinline__ void mma16816(float* d, const uint32_t* a, const uint32_t* b) {
    asm volatile(
        "mma.sync.aligned.m16n8k16.row.col.f32.bf16.bf16.f32 "
        "{%0,%1,%2,%3}, {%4,%5,%6,%7}, {%8,%9}, {%0,%1,%2,%3};"
        : "+f"(d[0]), "+f"(d[1]), "+f"(d[2]), "+f"(d[3])
        : "r"(a[0]), "r"(a[1]), "r"(a[2]), "r"(a[3]), "r"(b[0]), "r"(b[1]));
}

// ---------------- degree / zero / CSR ----------------
__global__ void k_zero() {
    int i = blockIdx.x * blockDim.x + threadIdx.x;
    if (i < NN) g_deg[i] = 0;
    if (i < GGR * DEMB) g_hg[i] = 0.f;
}
__global__ void k_deg_count(const int* __restrict__ ei) {
    int e = blockIdx.x * blockDim.x + threadIdx.x;
    if (e < EE) atomicAdd(&g_deg[ei[EE + e]], 1);
}
// scan pass 1: block-local exclusive scan of deg; also computes dinv.
__global__ __launch_bounds__(256) void k_scan1() {
    __shared__ int ws[8];
    int i = blockIdx.x * 256 + threadIdx.x;
    int lane = threadIdx.x & 31, w = threadIdx.x >> 5;
    int v = (i < NN) ? g_deg[i] : 0;
    if (i < NN) g_dinv[i] = rsqrtf((float)v + 1.0f);
    int x = v;
#pragma unroll
    for (int o = 1; o < 32; o <<= 1) {
        int t = __shfl_up_sync(0xffffffffu, x, o);
        if (lane >= o) x += t;
    }
    if (lane == 31) ws[w] = x;
    __syncthreads();
    if (w == 0 && lane < 8) {
        int y = ws[lane];
#pragma unroll
        for (int o = 1; o < 8; o <<= 1) {
            int t = __shfl_up_sync(0xffu, y, o);
            if (lane >= o) y += t;
        }
        ws[lane] = y;
    }
    __syncthreads();
    int base = (w > 0) ? ws[w - 1] : 0;
    if (i < NN) g_off[i] = base + x - v;
    if (threadIdx.x == 255) g_bsum[blockIdx.x] = ws[7];
}
__global__ __launch_bounds__(256) void k_scan2(int nblk) {
    __shared__ int ws[8];
    int lane = threadIdx.x & 31, w = threadIdx.x >> 5;
    int v = (threadIdx.x < nblk) ? g_bsum[threadIdx.x] : 0;
    int x = v;
#pragma unroll
    for (int o = 1; o < 32; o <<= 1) {
        int t = __shfl_up_sync(0xffffffffu, x, o);
        if (lane >= o) x += t;
    }
    if (lane == 31) ws[w] = x;
    __syncthreads();
    if (w == 0 && lane < 8) {
        int y = ws[lane];
#pragma unroll
        for (int o = 1; o < 8; o <<= 1) {
            int t = __shfl_up_sync(0xffu, y, o);
            if (lane >= o) y += t;
        }
        ws[lane] = y;
    }
    __syncthreads();
    int base = (w > 0) ? ws[w - 1] : 0;
    if (threadIdx.x < nblk) g_bsum[threadIdx.x] = base + x - v;
}
__global__ void k_scan3() {
    int i = blockIdx.x * blockDim.x + threadIdx.x;
    if (i < NN) {
        int o = g_off[i] + g_bsum[i >> 8];
        g_off[i] = o;
        g_cur[i] = o;
    }
}
__global__ void k_fill(const int* __restrict__ ei) {
    int e = blockIdx.x * blockDim.x + threadIdx.x;
    if (e < EE) {
        int s = ei[e], d = ei[EE + e];
        int pos = atomicAdd(&g_cur[d], 1);
        g_csr[pos] = s;
    }
}

// ---------------- fused conversions: x + 3 weights, one launch ----------------
#define W1SZ (256 * 128)
#define W2SZ (256 * 256)
#define W3SZ (128 * 256)
#define XSZ  (NN * 128)
__global__ void k_cvt_all(const float* __restrict__ x, const float* __restrict__ W1,
                          const float* __restrict__ W2, const float* __restrict__ W3)
{
    int idx = blockIdx.x * blockDim.x + threadIdx.x;
    float v;
    __nv_bfloat16 *oh, *ol;
    int o;
    if (idx < XSZ) {
        int row = idx >> 7, col = idx & 127;
        v = (col < FIN) ? x[row * FIN + col] : 0.f;
        oh = g_xA_hi; ol = g_xA_lo; o = idx;
    } else if (idx < XSZ + W1SZ) {
        o = idx - XSZ;                      // [N=256][KP=128], K=92
        int n = o >> 7, k = o & 127;
        v = (k < FIN) ? W1[k * DH + n] : 0.f;
        oh = g_w1_hi; ol = g_w1_lo;
    } else if (idx < XSZ + W1SZ + W2SZ) {
        o = idx - XSZ - W1SZ;               // [N=256][KP=256], K=256
        int n = o >> 8, k = o & 255;
        v = W2[k * DH + n];
        oh = g_w2_hi; ol = g_w2_lo;
    } else if (idx < XSZ + W1SZ + W2SZ + W3SZ) {
        o = idx - XSZ - W1SZ - W2SZ;        // [N=128][KP=256], K=256
        int n = o >> 8, k = o & 255;
        v = W3[k * DEMB + n];
        oh = g_w3_hi; ol = g_w3_lo;
    } else return;
    float h = __bfloat162float(__float2bfloat16(v));
    oh[o] = __float2bfloat16(v);
    ol[o] = __float2bfloat16(v - h);
}

// ---------------- mma.sync bf16x3 GEMM (sync loads, 64KB smem) ----------------
// C[128 x 128] tile per CTA.  D = Ah*Bh^T + Ah*Bl^T + Al*Bh^T, fp32 accum in regs.
#define SM_AH 0
#define SM_AL 16384
#define SM_BH 32768
#define SM_BL 49152
#define SMEM_BYTES 65536

template <int KP, int EPI>
__global__ __launch_bounds__(256) void k_mma(
    const __nv_bfloat16* __restrict__ Ah, const __nv_bfloat16* __restrict__ Al,
    const __nv_bfloat16* __restrict__ Bh, const __nv_bfloat16* __restrict__ Bl,
    const float* __restrict__ bias, float* __restrict__ C,
    __nv_bfloat16* __restrict__ Ohi, __nv_bfloat16* __restrict__ Olo, int Nfull)
{
    extern __shared__ __align__(128) char smem[];
    const uint32_t sb = smem_u32(smem);
    const int tid = threadIdx.x, wid = tid >> 5, lid = tid & 31;
    const int bm = blockIdx.y * 128;
    const int bn = blockIdx.x * 128;
    const int warp_m = wid & 3;   // 4 m-groups of 32 rows
    const int warp_n = wid >> 2;  // 2 n-groups of 64 cols

    float acc[2][8][4];
#pragma unroll
    for (int mt = 0; mt < 2; mt++)
#pragma unroll
        for (int nt = 0; nt < 8; nt++)
#pragma unroll
            for (int q = 0; q < 4; q++) acc[mt][nt][q] = 0.f;

    const int a_r = (lid & 7) + ((lid >> 3) & 1) * 8;
    const int a_u = (lid >> 4) & 1;
    const int b_r = (lid & 7) + ((lid >> 4) & 1) * 8;
    const int b_u = (lid >> 3) & 1;

    constexpr int NKC = KP / 64;
    for (int kc = 0; kc < NKC; kc++) {
        // load 4 tiles of [128 rows x 64 bf16], SW128-swizzled 16B units
#pragma unroll
        for (int i = 0; i < 4; i++) {
            int idx = tid + i * 256;          // 0..1023
            int r = idx >> 3, c16 = idx & 7;
            uint32_t so = (uint32_t)(r * 128 + ((c16 ^ (r & 7)) * 16));
            size_t ga = (size_t)(bm + r) * KP + kc * 64 + c16 * 8;
            size_t gb = (size_t)(bn + r) * KP + kc * 64 + c16 * 8;
            *(uint4*)(smem + SM_AH + so) = *(const uint4*)(Ah + ga);
            *(uint4*)(smem + SM_AL + so) = *(const uint4*)(Al + ga);
            *(uint4*)(smem + SM_BH + so) = *(const uint4*)(Bh + gb);
            *(uint4*)(smem + SM_BL + so) = *(const uint4*)(Bl + gb);
        }
        __syncthreads();

#pragma unroll
        for (int k16 = 0; k16 < 4; k16++) {
            uint32_t ah[2][4], al[2][4];
#pragma unroll
            for (int mt = 0; mt < 2; mt++) {
                int row = warp_m * 32 + mt * 16 + a_r;
                int u = k16 * 2 + a_u;
                uint32_t off = (uint32_t)(row * 128 + ((u ^ (row & 7)) * 16));
                ldsm_x4(ah[mt][0], ah[mt][1], ah[mt][2], ah[mt][3], sb + SM_AH + off);
                ldsm_x4(al[mt][0], al[mt][1], al[mt][2], al[mt][3], sb + SM_AL + off);
            }
            uint32_t bh[8][2], bl[8][2];
#pragma unroll
            for (int g = 0; g < 4; g++) {
                int row = warp_n * 64 + g * 16 + b_r;
                int u = k16 * 2 + b_u;
                uint32_t off = (uint32_t)(row * 128 + ((u ^ (row & 7)) * 16));
                ldsm_x4(bh[2 * g][0], bh[2 * g][1], bh[2 * g + 1][0], bh[2 * g + 1][1],
                        sb + SM_BH + off);
                ldsm_x4(bl[2 * g][0], bl[2 * g][1], bl[2 * g + 1][0], bl[2 * g + 1][1],
                        sb + SM_BL + off);
            }
#pragma unroll
            for (int mt = 0; mt < 2; mt++)
#pragma unroll
                for (int nt = 0; nt < 8; nt++) {
                    mma16816(acc[mt][nt], ah[mt], bh[nt]);
                    mma16816(acc[mt][nt], ah[mt], bl[nt]);
                    mma16816(acc[mt][nt], al[mt], bh[nt]);
                }
        }
        __syncthreads();
    }

    // epilogue straight from accumulator fragments
    const int r_base = bm + warp_m * 32 + (lid >> 2);
    const int c_base = bn + warp_n * 64 + (lid & 3) * 2;
#pragma unroll
    for (int mt = 0; mt < 2; mt++) {
#pragma unroll
        for (int h = 0; h < 2; h++) {
            int row = r_base + mt * 16 + h * 8;
            if (row >= NN) continue;
            if (EPI == 0) {
                float* cp = C + (size_t)row * Nfull;
#pragma unroll
                for (int nt = 0; nt < 8; nt++) {
                    float2 v = make_float2(acc[mt][nt][2 * h], acc[mt][nt][2 * h + 1]);
                    *(float2*)(cp + c_base + nt * 8) = v;
                }
            } else {
#pragma unroll
                for (int nt = 0; nt < 8; nt++) {
                    int col = c_base + nt * 8;
                    float v0 = lrelu(acc[mt][nt][2 * h] + bias[col]);
                    float v1 = lrelu(acc[mt][nt][2 * h + 1] + bias[col + 1]);
                    float h0 = __bfloat162float(__float2bfloat16(v0));
                    float h1 = __bfloat162float(__float2bfloat16(v1));
                    *(uint32_t*)(Ohi + (size_t)row * Nfull + col) = pack_bf16(v0, v1);
                    *(uint32_t*)(Olo + (size_t)row * Nfull + col) = pack_bf16(v0 - h0, v1 - h1);
                }
            }
        }
    }
}

// ---------------- fused aggregate + bias + LN + lrelu (+L2norm +pool / +bf16 emit) ----------------
// gather loop processes 2 edges/iter with independent accumulators (2x MLP).
template <int D, bool L2NORM, bool POOL, bool EMIT>
__global__ __launch_bounds__(256) void k_agg_ln(
    const float* __restrict__ xw, const float* __restrict__ bias,
    const float* __restrict__ gam, const float* __restrict__ bet,
    const int* __restrict__ batch, float* __restrict__ out,
    __nv_bfloat16* __restrict__ Ohi, __nv_bfloat16* __restrict__ Olo)
{
    int row = (blockIdx.x * blockDim.x + threadIdx.x) >> 5;
    int lane = threadIdx.x & 31;
    if (row >= NN) return;
    constexpr int P4 = D / 128;
    const float4* xw4 = (const float4*)xw;
    float di = g_dinv[row];

    float4 acc[P4], acc2[P4];
    {
        float s = di * di;
        size_t rb = (size_t)row * (D / 4);
#pragma unroll
        for (int j = 0; j < P4; j++) {
            float4 v = xw4[rb + lane + 32 * j];
            acc[j] = make_float4(v.x * s, v.y * s, v.z * s, v.w * s);
            acc2[j] = make_float4(0.f, 0.f, 0.f, 0.f);
        }
    }
    int o0 = g_off[row];
    int dg = g_deg[row];
    int e = 0;
    for (; e + 2 <= dg; e += 2) {
        int s0 = g_csr[o0 + e];
        int s1 = g_csr[o0 + e + 1];
        float n0 = g_dinv[s0] * di;
        float n1 = g_dinv[s1] * di;
        size_t b0 = (size_t)s0 * (D / 4);
        size_t b1 = (size_t)s1 * (D / 4);
#pragma unroll
        for (int j = 0; j < P4; j++) {
            float4 v0 = xw4[b0 + lane + 32 * j];
            float4 v1 = xw4[b1 + lane + 32 * j];
            acc[j].x = fmaf(v0.x, n0, acc[j].x);
            acc[j].y = fmaf(v0.y, n0, acc[j].y);
            acc[j].z = fmaf(v0.z, n0, acc[j].z);
            acc[j].w = fmaf(v0.w, n0, acc[j].w);
            acc2[j].x = fmaf(v1.x, n1, acc2[j].x);
            acc2[j].y = fmaf(v1.y, n1, acc2[j].y);
            acc2[j].z = fmaf(v1.z, n1, acc2[j].z);
            acc2[j].w = fmaf(v1.w, n1, acc2[j].w);
        }
    }
    if (e < dg) {
        int s0 = g_csr[o0 + e];
        float n0 = g_dinv[s0] * di;
        size_t b0 = (size_t)s0 * (D / 4);
#pragma unroll
        for (int j = 0; j < P4; j++) {
            float4 v0 = xw4[b0 + lane + 32 * j];
            acc[j].x = fmaf(v0.x, n0, acc[j].x);
            acc[j].y = fmaf(v0.y, n0, acc[j].y);
            acc[j].z = fmaf(v0.z, n0, acc[j].z);
            acc[j].w = fmaf(v0.w, n0, acc[j].w);
        }
    }
#pragma unroll
    for (int j = 0; j < P4; j++) {
        acc[j].x += acc2[j].x; acc[j].y += acc2[j].y;
        acc[j].z += acc2[j].z; acc[j].w += acc2[j].w;
    }

    const float4* bias4 = (const float4*)bias;
    float s = 0.f;
#pragma unroll
    for (int j = 0; j < P4; j++) {
        float4 bb = bias4[lane + 32 * j];
        acc[j].x += bb.x; acc[j].y += bb.y; acc[j].z += bb.z; acc[j].w += bb.w;
        s += acc[j].x + acc[j].y + acc[j].z + acc[j].w;
    }
    s = warp_sum(s);
    float mu = s * (1.0f / D);
    float q = 0.f;
#pragma unroll
    for (int j = 0; j < P4; j++) {
        float dx = acc[j].x - mu, dy = acc[j].y - mu;
        float dz = acc[j].z - mu, dw = acc[j].w - mu;
        q += dx * dx + dy * dy + dz * dz + dw * dw;
    }
    q = warp_sum(q);
    float r = rsqrtf(q * (1.0f / D) + EPSLN);

    const float4* gam4 = (const float4*)gam;
    const float4* bet4 = (const float4*)bet;
    float ss = 0.f;
#pragma unroll
    for (int j = 0; j < P4; j++) {
        float4 g = gam4[lane + 32 * j];
        float4 b = bet4[lane + 32 * j];
        float4 y;
        y.x = lrelu((acc[j].x - mu) * r * g.x + b.x);
        y.y = lrelu((acc[j].y - mu) * r * g.y + b.y);
        y.z = lrelu((acc[j].z - mu) * r * g.z + b.z);
        y.w = lrelu((acc[j].w - mu) * r * g.w + b.w);
        acc[j] = y;
        ss += y.x * y.x + y.y * y.y + y.z * y.z + y.w * y.w;
    }
    if (L2NORM) {
        ss = warp_sum(ss);
        float inv = 1.0f / fmaxf(sqrtf(ss), 1e-12f);
#pragma unroll
        for (int j = 0; j < P4; j++) {
            acc[j].x *= inv; acc[j].y *= inv; acc[j].z *= inv; acc[j].w *= inv;
        }
    }
    if (EMIT) {
#pragma unroll
        for (int j = 0; j < P4; j++) {
            float4 y = acc[j];
            float hx = __bfloat162float(__float2bfloat16(y.x));
            float hy = __bfloat162float(__float2bfloat16(y.y));
            float hz = __bfloat162float(__float2bfloat16(y.z));
            float hw = __bfloat162float(__float2bfloat16(y.w));
            uint2 vh = make_uint2(pack_bf16(y.x, y.y), pack_bf16(y.z, y.w));
            uint2 vl = make_uint2(pack_bf16(y.x - hx, y.y - hy), pack_bf16(y.z - hz, y.w - hw));
            size_t o = (size_t)row * D + 4 * lane + 128 * j;
            *(uint2*)(Ohi + o) = vh;
            *(uint2*)(Olo + o) = vl;
        }
    } else {
        float4* o4 = (float4*)out + (size_t)row * (D / 4);
#pragma unroll
        for (int j = 0; j < P4; j++) o4[lane + 32 * j] = acc[j];
    }
    if (POOL) {
        int b = batch[row];
#pragma unroll
        for (int j = 0; j < P4; j++)
            red_add_v4(g_hg + (size_t)b * DEMB + (4 * lane + 128 * j), acc[j]);
    }
}

// ---------------- final MLP ----------------
__global__ __launch_bounds__(64) void k_mlp(
    const float* __restrict__ W1, const float* __restrict__ b1,
    const float* __restrict__ W2, const float* __restrict__ b2,
    float* __restrict__ out)
{
    int g = blockIdx.x;
    int t = threadIdx.x;
    __shared__ float sh[DEMB];
    __shared__ float red[2];
    sh[t] = g_hg[(size_t)g * DEMB + t];
    sh[t + 64] = g_hg[(size_t)g * DEMB + 64 + t];
    __syncthreads();
    float s = b1[t];
#pragma unroll
    for (int k = 0; k < DEMB; k++) s = fmaf(sh[k], W1[k * 64 + t], s);
    s = lrelu(s);
    s *= W2[t];
    s = warp_sum(s);
    if ((t & 31) == 0) red[t >> 5] = s;
    __syncthreads();
    if (t == 0) out[g] = red[0] + red[1] + b2[0];
}

// ---------------- launch ----------------
extern "C" void kernel_launch(void* const* d_in, const int* in_sizes, int n_in,
                              void* d_out, int out_size)
{
    const float* x     = (const float*)d_in[0];
    const int*   ei    = (const int*)  d_in[1];
    const int*   batch = (const int*)  d_in[2];
    const float* nfcW  = (const float*)d_in[3];
    const float* nfcb  = (const float*)d_in[4];
    const float* gn1g  = (const float*)d_in[5];
    const float* gn1b  = (const float*)d_in[6];
    const float* gc1W  = (const float*)d_in[7];
    const float* gc1b  = (const float*)d_in[8];
    const float* gn2g  = (const float*)d_in[9];
    const float* gn2b  = (const float*)d_in[10];
    const float* gc2W  = (const float*)d_in[11];
    const float* gc2b  = (const float*)d_in[12];
    const float* fc1W  = (const float*)d_in[13];
    const float* fc1b  = (const float*)d_in[14];
    const float* fc2W  = (const float*)d_in[15];
    const float* fc2b  = (const float*)d_in[16];

    float* out   = (float*)d_out;
    float* outHa = out + GGR;

    float* xw;  cudaGetSymbolAddress((void**)&xw, g_xw);
    __nv_bfloat16 *xAh, *xAl, *h1h, *h1l, *h2h, *h2l;
    __nv_bfloat16 *w1h, *w1l, *w2h, *w2l, *w3h, *w3l;
    cudaGetSymbolAddress((void**)&xAh, g_xA_hi); cudaGetSymbolAddress((void**)&xAl, g_xA_lo);
    cudaGetSymbolAddress((void**)&h1h, g_h1_hi); cudaGetSymbolAddress((void**)&h1l, g_h1_lo);
    cudaGetSymbolAddress((void**)&h2h, g_h2_hi); cudaGetSymbolAddress((void**)&h2l, g_h2_lo);
    cudaGetSymbolAddress((void**)&w1h, g_w1_hi); cudaGetSymbolAddress((void**)&w1l, g_w1_lo);
    cudaGetSymbolAddress((void**)&w2h, g_w2_hi); cudaGetSymbolAddress((void**)&w2l, g_w2_lo);
    cudaGetSymbolAddress((void**)&w3h, g_w3_hi); cudaGetSymbolAddress((void**)&w3l, g_w3_lo);

    cudaFuncSetAttribute(k_mma<128, 1>, cudaFuncAttributeMaxDynamicSharedMemorySize, SMEM_BYTES);
    cudaFuncSetAttribute(k_mma<256, 0>, cudaFuncAttributeMaxDynamicSharedMemorySize, SMEM_BYTES);

    const int NB = (NN + 255) / 256;
    const int MBLK = NNP / 128;  // 391

    // 1) degree + dinv + CSR build
    k_zero<<<(GGR * DEMB + 255) / 256, 256>>>();
    k_deg_count<<<(EE + 255) / 256, 256>>>(ei);
    k_scan1<<<NB, 256>>>();
    k_scan2<<<1, 256>>>(NB);
    k_scan3<<<NB, 256>>>();
    k_fill<<<(EE + 255) / 256, 256>>>(ei);

    // 2) fused operand conversions (x + all 3 weights)
    k_cvt_all<<<(XSZ + W1SZ + W2SZ + W3SZ + 255) / 256, 256>>>(x, nfcW, gc1W, gc2W);

    // 3) encoder: h1 = lrelu(x @ nfcW + b) -> bf16 hi/lo
    k_mma<128, 1><<<dim3(2, MBLK), 256, SMEM_BYTES>>>(
        xAh, xAl, w1h, w1l, nfcb, nullptr, h1h, h1l, DH);

    // 4) conv1: xw = h1 @ gc1W ; agg+LN+lrelu -> h2 bf16 hi/lo
    k_mma<256, 0><<<dim3(2, MBLK), 256, SMEM_BYTES>>>(
        h1h, h1l, w2h, w2l, nullptr, xw, nullptr, nullptr, DH);
    k_agg_ln<DH, false, false, true><<<(NN * 32 + 255) / 256, 256>>>(
        xw, gc1b, gn1g, gn1b, batch, nullptr, h2h, h2l);

    // 5) conv2: xw = h2 @ gc2W ; agg+LN+lrelu+L2norm+pool -> outHa
    k_mma<256, 0><<<dim3(1, MBLK), 256, SMEM_BYTES>>>(
        h2h, h2l, w3h, w3l, nullptr, xw, nullptr, nullptr, DEMB);
    k_agg_ln<DEMB, true, true, false><<<(NN * 32 + 255) / 256, 256>>>(
        xw, gc2b, gn2g, gn2b, batch, outHa, nullptr, nullptr);

    // 6) MLP head
    k_mlp<<<GGR, 64>>>(fc1W, fc1b, fc2W, fc2b, out);
}

// round 12
// speedup vs baseline: 1.3824x; 1.1403x over previous
#include <cuda_runtime.h>
#include <cuda_fp16.h>
#include <math.h>
#include <stdint.h>

#define NN   50000
#define NNP  50048              // padded to multiple of 128
#define EE   400000
#define GGR  500
#define FIN  92
#define DH   256
#define DEMB 128
#define EPSLN 1e-5f

// ---------------- scratch (no allocations allowed) ----------------
__device__ float g_xw[NN * DH];            // GEMM fp32 output (pre-aggregation)
__device__ float g_dinv[NN];
__device__ int   g_deg[NN];
__device__ int   g_off[NN];
__device__ int   g_cur[NN];
__device__ int   g_csr[EE];
__device__ int   g_bsum[256];
__device__ float g_hg[GGR * DEMB];

// fp16 operand buffers. A-side split hi/lo; weights single fp16.
__device__ __half g_xA_hi[NNP * 128];
__device__ __half g_xA_lo[NNP * 128];
__device__ __half g_h1_hi[NNP * 256];
__device__ __half g_h1_lo[NNP * 256];
__device__ __half g_h2_hi[NNP * 256];
__device__ __half g_h2_lo[NNP * 256];
__device__ __half g_w1[256 * 128];   // nfcW^T padded [N=256][KP=128]
__device__ __half g_w2[256 * 256];   // gc1W^T
__device__ __half g_w3[128 * 256];   // gc2W^T

// ---------------- small helpers ----------------
__device__ __forceinline__ float warp_sum(float v) {
#pragma unroll
    for (int o = 16; o > 0; o >>= 1) v += __shfl_xor_sync(0xffffffffu, v, o);
    return v;
}
__device__ __forceinline__ float lrelu(float v) { return v > 0.f ? v : 0.01f * v; }

__device__ __forceinline__ void red_add_v4(float* p, float4 v) {
    asm volatile("red.global.add.v4.f32 [%0], {%1, %2, %3, %4};"
                 :: "l"(p), "f"(v.x), "f"(v.y), "f"(v.z), "f"(v.w) : "memory");
}
__device__ __forceinline__ uint32_t pack_f16(float a, float b) {
    __half2 t = __halves2half2(__float2half(a), __float2half(b));
    return *reinterpret_cast<uint32_t*>(&t);
}
__device__ __forceinline__ uint32_t smem_u32(const void* p) {
    return (uint32_t)__cvta_generic_to_shared(p);
}
__device__ __forceinline__ void ldsm_x4(uint32_t& r0, uint32_t& r1, uint32_t& r2,
                                        uint32_t& r3, uint32_t addr) {
    asm volatile("ldmatrix.sync.aligned.m8n8.x4.shared.b16 {%0,%1,%2,%3}, [%4];"
                 : "=r"(r0), "=r"(r1), "=r"(r2), "=r"(r3) : "r"(addr));
}
__device__ __forceinline__ void mma16816(float* d, const uint32_t* a, const uint32_t* b) {
    asm volatile(
        "mma.sync.aligned.m16n8k16.row.col.f32.f16.f16.f32 "
        "{%0,%1,%2,%3}, {%4,%5,%6,%7}, {%8,%9}, {%0,%1,%2,%3};"
        : "+f"(d[0]), "+f"(d[1]), "+f"(d[2]), "+f"(d[3])
        : "r"(a[0]), "r"(a[1]), "r"(a[2]), "r"(a[3]), "r"(b[0]), "r"(b[1]));
}

// ---------------- degree / zero / CSR ----------------
__global__ void k_zero() {
    int i = blockIdx.x * blockDim.x + threadIdx.x;
    if (i < NN) g_deg[i] = 0;
    if (i < GGR * DEMB) g_hg[i] = 0.f;
}
__global__ void k_deg_count(const int* __restrict__ ei) {
    int e = blockIdx.x * blockDim.x + threadIdx.x;
    if (e < EE) atomicAdd(&g_deg[ei[EE + e]], 1);
}
// scan pass 1: block-local exclusive scan of deg; also computes dinv.
__global__ __launch_bounds__(256) void k_scan1() {
    __shared__ int ws[8];
    int i = blockIdx.x * 256 + threadIdx.x;
    int lane = threadIdx.x & 31, w = threadIdx.x >> 5;
    int v = (i < NN) ? g_deg[i] : 0;
    if (i < NN) g_dinv[i] = rsqrtf((float)v + 1.0f);
    int x = v;
#pragma unroll
    for (int o = 1; o < 32; o <<= 1) {
        int t = __shfl_up_sync(0xffffffffu, x, o);
        if (lane >= o) x += t;
    }
    if (lane == 31) ws[w] = x;
    __syncthreads();
    if (w == 0 && lane < 8) {
        int y = ws[lane];
#pragma unroll
        for (int o = 1; o < 8; o <<= 1) {
            int t = __shfl_up_sync(0xffu, y, o);
            if (lane >= o) y += t;
        }
        ws[lane] = y;
    }
    __syncthreads();
    int base = (w > 0) ? ws[w - 1] : 0;
    if (i < NN) g_off[i] = base + x - v;
    if (threadIdx.x == 255) g_bsum[blockIdx.x] = ws[7];
}
__global__ __launch_bounds__(256) void k_scan2(int nblk) {
    __shared__ int ws[8];
    int lane = threadIdx.x & 31, w = threadIdx.x >> 5;
    int v = (threadIdx.x < nblk) ? g_bsum[threadIdx.x] : 0;
    int x = v;
#pragma unroll
    for (int o = 1; o < 32; o <<= 1) {
        int t = __shfl_up_sync(0xffffffffu, x, o);
        if (lane >= o) x += t;
    }
    if (lane == 31) ws[w] = x;
    __syncthreads();
    if (w == 0 && lane < 8) {
        int y = ws[lane];
#pragma unroll
        for (int o = 1; o < 8; o <<= 1) {
            int t = __shfl_up_sync(0xffu, y, o);
            if (lane >= o) y += t;
        }
        ws[lane] = y;
    }
    __syncthreads();
    int base = (w > 0) ? ws[w - 1] : 0;
    if (threadIdx.x < nblk) g_bsum[threadIdx.x] = base + x - v;
}
__global__ void k_scan3() {
    int i = blockIdx.x * blockDim.x + threadIdx.x;
    if (i < NN) {
        int o = g_off[i] + g_bsum[i >> 8];
        g_off[i] = o;
        g_cur[i] = o;
    }
}
__global__ void k_fill(const int* __restrict__ ei) {
    int e = blockIdx.x * blockDim.x + threadIdx.x;
    if (e < EE) {
        int s = ei[e], d = ei[EE + e];
        int pos = atomicAdd(&g_cur[d], 1);
        g_csr[pos] = s;
    }
}

// ---------------- fused conversions: x (split) + 3 weights (single fp16) ----------------
#define W1SZ (256 * 128)
#define W2SZ (256 * 256)
#define W3SZ (128 * 256)
#define XSZ  (NN * 128)
__global__ void k_cvt_all(const float* __restrict__ x, const float* __restrict__ W1,
                          const float* __restrict__ W2, const float* __restrict__ W3)
{
    int idx = blockIdx.x * blockDim.x + threadIdx.x;
    if (idx < XSZ) {
        int row = idx >> 7, col = idx & 127;
        float v = (col < FIN) ? x[row * FIN + col] : 0.f;
        __half h = __float2half(v);
        g_xA_hi[idx] = h;
        g_xA_lo[idx] = __float2half(v - __half2float(h));
        return;
    }
    int o;
    float v;
    __half* ow;
    if (idx < XSZ + W1SZ) {
        o = idx - XSZ;                      // [N=256][KP=128], K=92
        int n = o >> 7, k = o & 127;
        v = (k < FIN) ? W1[k * DH + n] : 0.f;
        ow = g_w1;
    } else if (idx < XSZ + W1SZ + W2SZ) {
        o = idx - XSZ - W1SZ;               // [N=256][KP=256]
        int n = o >> 8, k = o & 255;
        v = W2[k * DH + n];
        ow = g_w2;
    } else if (idx < XSZ + W1SZ + W2SZ + W3SZ) {
        o = idx - XSZ - W1SZ - W2SZ;        // [N=128][KP=256]
        int n = o >> 8, k = o & 255;
        v = W3[k * DEMB + n];
        ow = g_w3;
    } else return;
    ow[o] = __float2half(v);
}

// ---------------- mma.sync fp16 A-split GEMM (2 MMAs/tile, 48KB smem) ----------------
// C[128 x 128] tile per CTA.  D = Ah*Bh^T + Al*Bh^T, fp32 accum in regs.
#define SM_AH 0
#define SM_AL 16384
#define SM_BH 32768
#define SMEM_BYTES 49152

template <int KP, int EPI>
__global__ __launch_bounds__(256) void k_mma(
    const __half* __restrict__ Ah, const __half* __restrict__ Al,
    const __half* __restrict__ Bh,
    const float* __restrict__ bias, float* __restrict__ C,
    __half* __restrict__ Ohi, __half* __restrict__ Olo, int Nfull)
{
    extern __shared__ __align__(128) char smem[];
    const uint32_t sb = smem_u32(smem);
    const int tid = threadIdx.x, wid = tid >> 5, lid = tid & 31;
    const int bm = blockIdx.y * 128;
    const int bn = blockIdx.x * 128;
    const int warp_m = wid & 3;   // 4 m-groups of 32 rows
    const int warp_n = wid >> 2;  // 2 n-groups of 64 cols

    float acc[2][8][4];
#pragma unroll
    for (int mt = 0; mt < 2; mt++)
#pragma unroll
        for (int nt = 0; nt < 8; nt++)
#pragma unroll
            for (int q = 0; q < 4; q++) acc[mt][nt][q] = 0.f;

    const int a_r = (lid & 7) + ((lid >> 3) & 1) * 8;
    const int a_u = (lid >> 4) & 1;
    const int b_r = (lid & 7) + ((lid >> 4) & 1) * 8;
    const int b_u = (lid >> 3) & 1;

    constexpr int NKC = KP / 64;
    for (int kc = 0; kc < NKC; kc++) {
        // load 3 tiles of [128 rows x 64 fp16], SW128-swizzled 16B units
#pragma unroll
        for (int i = 0; i < 4; i++) {
            int idx = tid + i * 256;          // 0..1023
            int r = idx >> 3, c16 = idx & 7;
            uint32_t so = (uint32_t)(r * 128 + ((c16 ^ (r & 7)) * 16));
            size_t ga = (size_t)(bm + r) * KP + kc * 64 + c16 * 8;
            size_t gb = (size_t)(bn + r) * KP + kc * 64 + c16 * 8;
            *(uint4*)(smem + SM_AH + so) = *(const uint4*)(Ah + ga);
            *(uint4*)(smem + SM_AL + so) = *(const uint4*)(Al + ga);
            *(uint4*)(smem + SM_BH + so) = *(const uint4*)(Bh + gb);
        }
        __syncthreads();

#pragma unroll
        for (int k16 = 0; k16 < 4; k16++) {
            uint32_t ah[2][4], al[2][4];
#pragma unroll
            for (int mt = 0; mt < 2; mt++) {
                int row = warp_m * 32 + mt * 16 + a_r;
                int u = k16 * 2 + a_u;
                uint32_t off = (uint32_t)(row * 128 + ((u ^ (row & 7)) * 16));
                ldsm_x4(ah[mt][0], ah[mt][1], ah[mt][2], ah[mt][3], sb + SM_AH + off);
                ldsm_x4(al[mt][0], al[mt][1], al[mt][2], al[mt][3], sb + SM_AL + off);
            }
            uint32_t bh[8][2];
#pragma unroll
            for (int g = 0; g < 4; g++) {
                int row = warp_n * 64 + g * 16 + b_r;
                int u = k16 * 2 + b_u;
                uint32_t off = (uint32_t)(row * 128 + ((u ^ (row & 7)) * 16));
                ldsm_x4(bh[2 * g][0], bh[2 * g][1], bh[2 * g + 1][0], bh[2 * g + 1][1],
                        sb + SM_BH + off);
            }
#pragma unroll
            for (int mt = 0; mt < 2; mt++)
#pragma unroll
                for (int nt = 0; nt < 8; nt++) {
                    mma16816(acc[mt][nt], ah[mt], bh[nt]);
                    mma16816(acc[mt][nt], al[mt], bh[nt]);
                }
        }
        __syncthreads();
    }

    // epilogue straight from accumulator fragments
    const int r_base = bm + warp_m * 32 + (lid >> 2);
    const int c_base = bn + warp_n * 64 + (lid & 3) * 2;
#pragma unroll
    for (int mt = 0; mt < 2; mt++) {
#pragma unroll
        for (int h = 0; h < 2; h++) {
            int row = r_base + mt * 16 + h * 8;
            if (row >= NN) continue;
            if (EPI == 0) {
                float* cp = C + (size_t)row * Nfull;
#pragma unroll
                for (int nt = 0; nt < 8; nt++) {
                    float2 v = make_float2(acc[mt][nt][2 * h], acc[mt][nt][2 * h + 1]);
                    *(float2*)(cp + c_base + nt * 8) = v;
                }
            } else {
#pragma unroll
                for (int nt = 0; nt < 8; nt++) {
                    int col = c_base + nt * 8;
                    float v0 = lrelu(acc[mt][nt][2 * h] + bias[col]);
                    float v1 = lrelu(acc[mt][nt][2 * h + 1] + bias[col + 1]);
                    float h0 = __half2float(__float2half(v0));
                    float h1 = __half2float(__float2half(v1));
                    *(uint32_t*)(Ohi + (size_t)row * Nfull + col) = pack_f16(v0, v1);
                    *(uint32_t*)(Olo + (size_t)row * Nfull + col) = pack_f16(v0 - h0, v1 - h1);
                }
            }
        }
    }
}

// ---------------- fused aggregate + bias + LN + lrelu (+L2norm +pool / +fp16 emit) ----------------
template <int D, bool L2NORM, bool POOL, bool EMIT>
__global__ __launch_bounds__(256) void k_agg_ln(
    const float* __restrict__ xw, const float* __restrict__ bias,
    const float* __restrict__ gam, const float* __restrict__ bet,
    const int* __restrict__ batch, float* __restrict__ out,
    __half* __restrict__ Ohi, __half* __restrict__ Olo)
{
    int row = (blockIdx.x * blockDim.x + threadIdx.x) >> 5;
    int lane = threadIdx.x & 31;
    if (row >= NN) return;
    constexpr int P4 = D / 128;
    const float4* xw4 = (const float4*)xw;
    float di = g_dinv[row];

    float4 acc[P4], acc2[P4];
    {
        float s = di * di;
        size_t rb = (size_t)row * (D / 4);
#pragma unroll
        for (int j = 0; j < P4; j++) {
            float4 v = xw4[rb + lane + 32 * j];
            acc[j] = make_float4(v.x * s, v.y * s, v.z * s, v.w * s);
            acc2[j] = make_float4(0.f, 0.f, 0.f, 0.f);
        }
    }
    int o0 = g_off[row];
    int dg = g_deg[row];
    int e = 0;
    for (; e + 2 <= dg; e += 2) {
        int s0 = g_csr[o0 + e];
        int s1 = g_csr[o0 + e + 1];
        float n0 = g_dinv[s0] * di;
        float n1 = g_dinv[s1] * di;
        size_t b0 = (size_t)s0 * (D / 4);
        size_t b1 = (size_t)s1 * (D / 4);
#pragma unroll
        for (int j = 0; j < P4; j++) {
            float4 v0 = xw4[b0 + lane + 32 * j];
            float4 v1 = xw4[b1 + lane + 32 * j];
            acc[j].x = fmaf(v0.x, n0, acc[j].x);
            acc[j].y = fmaf(v0.y, n0, acc[j].y);
            acc[j].z = fmaf(v0.z, n0, acc[j].z);
            acc[j].w = fmaf(v0.w, n0, acc[j].w);
            acc2[j].x = fmaf(v1.x, n1, acc2[j].x);
            acc2[j].y = fmaf(v1.y, n1, acc2[j].y);
            acc2[j].z = fmaf(v1.z, n1, acc2[j].z);
            acc2[j].w = fmaf(v1.w, n1, acc2[j].w);
        }
    }
    if (e < dg) {
        int s0 = g_csr[o0 + e];
        float n0 = g_dinv[s0] * di;
        size_t b0 = (size_t)s0 * (D / 4);
#pragma unroll
        for (int j = 0; j < P4; j++) {
            float4 v0 = xw4[b0 + lane + 32 * j];
            acc[j].x = fmaf(v0.x, n0, acc[j].x);
            acc[j].y = fmaf(v0.y, n0, acc[j].y);
            acc[j].z = fmaf(v0.z, n0, acc[j].z);
            acc[j].w = fmaf(v0.w, n0, acc[j].w);
        }
    }
#pragma unroll
    for (int j = 0; j < P4; j++) {
        acc[j].x += acc2[j].x; acc[j].y += acc2[j].y;
        acc[j].z += acc2[j].z; acc[j].w += acc2[j].w;
    }

    const float4* bias4 = (const float4*)bias;
    float s = 0.f;
#pragma unroll
    for (int j = 0; j < P4; j++) {
        float4 bb = bias4[lane + 32 * j];
        acc[j].x += bb.x; acc[j].y += bb.y; acc[j].z += bb.z; acc[j].w += bb.w;
        s += acc[j].x + acc[j].y + acc[j].z + acc[j].w;
    }
    s = warp_sum(s);
    float mu = s * (1.0f / D);
    float q = 0.f;
#pragma unroll
    for (int j = 0; j < P4; j++) {
        float dx = acc[j].x - mu, dy = acc[j].y - mu;
        float dz = acc[j].z - mu, dw = acc[j].w - mu;
        q += dx * dx + dy * dy + dz * dz + dw * dw;
    }
    q = warp_sum(q);
    float r = rsqrtf(q * (1.0f / D) + EPSLN);

    const float4* gam4 = (const float4*)gam;
    const float4* bet4 = (const float4*)bet;
    float ss = 0.f;
#pragma unroll
    for (int j = 0; j < P4; j++) {
        float4 g = gam4[lane + 32 * j];
        float4 b = bet4[lane + 32 * j];
        float4 y;
        y.x = lrelu((acc[j].x - mu) * r * g.x + b.x);
        y.y = lrelu((acc[j].y - mu) * r * g.y + b.y);
        y.z = lrelu((acc[j].z - mu) * r * g.z + b.z);
        y.w = lrelu((acc[j].w - mu) * r * g.w + b.w);
        acc[j] = y;
        ss += y.x * y.x + y.y * y.y + y.z * y.z + y.w * y.w;
    }
    if (L2NORM) {
        ss = warp_sum(ss);
        float inv = 1.0f / fmaxf(sqrtf(ss), 1e-12f);
#pragma unroll
        for (int j = 0; j < P4; j++) {
            acc[j].x *= inv; acc[j].y *= inv; acc[j].z *= inv; acc[j].w *= inv;
        }
    }
    if (EMIT) {
#pragma unroll
        for (int j = 0; j < P4; j++) {
            float4 y = acc[j];
            float hx = __half2float(__float2half(y.x));
            float hy = __half2float(__float2half(y.y));
            float hz = __half2float(__float2half(y.z));
            float hw = __half2float(__float2half(y.w));
            uint2 vh = make_uint2(pack_f16(y.x, y.y), pack_f16(y.z, y.w));
            uint2 vl = make_uint2(pack_f16(y.x - hx, y.y - hy), pack_f16(y.z - hz, y.w - hw));
            size_t o = (size_t)row * D + 4 * lane + 128 * j;
            *(uint2*)(Ohi + o) = vh;
            *(uint2*)(Olo + o) = vl;
        }
    } else {
        float4* o4 = (float4*)out + (size_t)row * (D / 4);
#pragma unroll
        for (int j = 0; j < P4; j++) o4[lane + 32 * j] = acc[j];
    }
    if (POOL) {
        int b = batch[row];
#pragma unroll
        for (int j = 0; j < P4; j++)
            red_add_v4(g_hg + (size_t)b * DEMB + (4 * lane + 128 * j), acc[j]);
    }
}

// ---------------- final MLP ----------------
__global__ __launch_bounds__(64) void k_mlp(
    const float* __restrict__ W1, const float* __restrict__ b1,
    const float* __restrict__ W2, const float* __restrict__ b2,
    float* __restrict__ out)
{
    int g = blockIdx.x;
    int t = threadIdx.x;
    __shared__ float sh[DEMB];
    __shared__ float red[2];
    sh[t] = g_hg[(size_t)g * DEMB + t];
    sh[t + 64] = g_hg[(size_t)g * DEMB + 64 + t];
    __syncthreads();
    float s = b1[t];
#pragma unroll
    for (int k = 0; k < DEMB; k++) s = fmaf(sh[k], W1[k * 64 + t], s);
    s = lrelu(s);
    s *= W2[t];
    s = warp_sum(s);
    if ((t & 31) == 0) red[t >> 5] = s;
    __syncthreads();
    if (t == 0) out[g] = red[0] + red[1] + b2[0];
}

// ---------------- launch ----------------
extern "C" void kernel_launch(void* const* d_in, const int* in_sizes, int n_in,
                              void* d_out, int out_size)
{
    const float* x     = (const float*)d_in[0];
    const int*   ei    = (const int*)  d_in[1];
    const int*   batch = (const int*)  d_in[2];
    const float* nfcW  = (const float*)d_in[3];
    const float* nfcb  = (const float*)d_in[4];
    const float* gn1g  = (const float*)d_in[5];
    const float* gn1b  = (const float*)d_in[6];
    const float* gc1W  = (const float*)d_in[7];
    const float* gc1b  = (const float*)d_in[8];
    const float* gn2g  = (const float*)d_in[9];
    const float* gn2b  = (const float*)d_in[10];
    const float* gc2W  = (const float*)d_in[11];
    const float* gc2b  = (const float*)d_in[12];
    const float* fc1W  = (const float*)d_in[13];
    const float* fc1b  = (const float*)d_in[14];
    const float* fc2W  = (const float*)d_in[15];
    const float* fc2b  = (const float*)d_in[16];

    float* out   = (float*)d_out;
    float* outHa = out + GGR;

    float* xw;  cudaGetSymbolAddress((void**)&xw, g_xw);
    __half *xAh, *xAl, *h1h, *h1l, *h2h, *h2l, *w1, *w2, *w3;
    cudaGetSymbolAddress((void**)&xAh, g_xA_hi); cudaGetSymbolAddress((void**)&xAl, g_xA_lo);
    cudaGetSymbolAddress((void**)&h1h, g_h1_hi); cudaGetSymbolAddress((void**)&h1l, g_h1_lo);
    cudaGetSymbolAddress((void**)&h2h, g_h2_hi); cudaGetSymbolAddress((void**)&h2l, g_h2_lo);
    cudaGetSymbolAddress((void**)&w1, g_w1);
    cudaGetSymbolAddress((void**)&w2, g_w2);
    cudaGetSymbolAddress((void**)&w3, g_w3);

    cudaFuncSetAttribute(k_mma<128, 1>, cudaFuncAttributeMaxDynamicSharedMemorySize, SMEM_BYTES);
    cudaFuncSetAttribute(k_mma<256, 0>, cudaFuncAttributeMaxDynamicSharedMemorySize, SMEM_BYTES);

    const int NB = (NN + 255) / 256;
    const int MBLK = NNP / 128;  // 391

    // 1) degree + dinv + CSR build
    k_zero<<<(GGR * DEMB + 255) / 256, 256>>>();
    k_deg_count<<<(EE + 255) / 256, 256>>>(ei);
    k_scan1<<<NB, 256>>>();
    k_scan2<<<1, 256>>>(NB);
    k_scan3<<<NB, 256>>>();
    k_fill<<<(EE + 255) / 256, 256>>>(ei);

    // 2) fused operand conversions (x split + 3 weights single fp16)
    k_cvt_all<<<(XSZ + W1SZ + W2SZ + W3SZ + 255) / 256, 256>>>(x, nfcW, gc1W, gc2W);

    // 3) encoder: h1 = lrelu(x @ nfcW + b) -> fp16 hi/lo
    k_mma<128, 1><<<dim3(2, MBLK), 256, SMEM_BYTES>>>(
        xAh, xAl, w1, nfcb, nullptr, h1h, h1l, DH);

    // 4) conv1: xw = h1 @ gc1W ; agg+LN+lrelu -> h2 fp16 hi/lo
    k_mma<256, 0><<<dim3(2, MBLK), 256, SMEM_BYTES>>>(
        h1h, h1l, w2, nullptr, xw, nullptr, nullptr, DH);
    k_agg_ln<DH, false, false, true><<<(NN * 32 + 255) / 256, 256>>>(
        xw, gc1b, gn1g, gn1b, batch, nullptr, h2h, h2l);

    // 5) conv2: xw = h2 @ gc2W ; agg+LN+lrelu+L2norm+pool -> outHa
    k_mma<256, 0><<<dim3(1, MBLK), 256, SMEM_BYTES>>>(
        h2h, h2l, w3, nullptr, xw, nullptr, nullptr, DEMB);
    k_agg_ln<DEMB, true, true, false><<<(NN * 32 + 255) / 256, 256>>>(
        xw, gc2b, gn2g, gn2b, batch, outHa, nullptr, nullptr);

    // 6) MLP head
    k_mlp<<<GGR, 64>>>(fc1W, fc1b, fc2W, fc2b, out);
}

// round 13
// speedup vs baseline: 1.4629x; 1.0583x over previous
#include <cuda_runtime.h>
#include <cuda_fp16.h>
#include <math.h>
#include <stdint.h>

#define NN   50000
#define NNP  50048              // padded to multiple of 128
#define EE   400000
#define GGR  500
#define FIN  92
#define DH   256
#define DEMB 128
#define EPSLN 1e-5f

// ---------------- scratch (no allocations allowed) ----------------
__device__ __half g_xw[NN * DH];           // GEMM output (pre-aggregation), fp16
__device__ float g_dinv[NN];
__device__ int   g_deg[NN];
__device__ int   g_off[NN];
__device__ int   g_cur[NN];
__device__ int   g_csr[EE];
__device__ int   g_bsum[256];
__device__ float g_hg[GGR * DEMB];

// fp16 operand buffers. A-side split hi/lo; weights single fp16.
__device__ __half g_xA_hi[NNP * 128];
__device__ __half g_xA_lo[NNP * 128];
__device__ __half g_h1_hi[NNP * 256];
__device__ __half g_h1_lo[NNP * 256];
__device__ __half g_h2_hi[NNP * 256];
__device__ __half g_h2_lo[NNP * 256];
__device__ __half g_w1[256 * 128];   // nfcW^T padded [N=256][KP=128]
__device__ __half g_w2[256 * 256];   // gc1W^T
__device__ __half g_w3[128 * 256];   // gc2W^T

// ---------------- small helpers ----------------
__device__ __forceinline__ float warp_sum(float v) {
#pragma unroll
    for (int o = 16; o > 0; o >>= 1) v += __shfl_xor_sync(0xffffffffu, v, o);
    return v;
}
__device__ __forceinline__ float lrelu(float v) { return v > 0.f ? v : 0.01f * v; }

__device__ __forceinline__ void red_add_v4(float* p, float4 v) {
    asm volatile("red.global.add.v4.f32 [%0], {%1, %2, %3, %4};"
                 :: "l"(p), "f"(v.x), "f"(v.y), "f"(v.z), "f"(v.w) : "memory");
}
__device__ __forceinline__ uint32_t pack_f16(float a, float b) {
    __half2 t = __halves2half2(__float2half(a), __float2half(b));
    return *reinterpret_cast<uint32_t*>(&t);
}
__device__ __forceinline__ uint32_t smem_u32(const void* p) {
    return (uint32_t)__cvta_generic_to_shared(p);
}
__device__ __forceinline__ void ldsm_x4(uint32_t& r0, uint32_t& r1, uint32_t& r2,
                                        uint32_t& r3, uint32_t addr) {
    asm volatile("ldmatrix.sync.aligned.m8n8.x4.shared.b16 {%0,%1,%2,%3}, [%4];"
                 : "=r"(r0), "=r"(r1), "=r"(r2), "=r"(r3) : "r"(addr));
}
__device__ __forceinline__ void mma16816(float* d, const uint32_t* a, const uint32_t* b) {
    asm volatile(
        "mma.sync.aligned.m16n8k16.row.col.f32.f16.f16.f32 "
        "{%0,%1,%2,%3}, {%4,%5,%6,%7}, {%8,%9}, {%0,%1,%2,%3};"
        : "+f"(d[0]), "+f"(d[1]), "+f"(d[2]), "+f"(d[3])
        : "r"(a[0]), "r"(a[1]), "r"(a[2]), "r"(a[3]), "r"(b[0]), "r"(b[1]));
}

// ---------------- degree / zero / CSR ----------------
__global__ void k_zero() {
    int i = blockIdx.x * blockDim.x + threadIdx.x;
    if (i < NN) g_deg[i] = 0;
    if (i < GGR * DEMB) g_hg[i] = 0.f;
}
__global__ void k_deg_count(const int* __restrict__ ei) {
    int e = blockIdx.x * blockDim.x + threadIdx.x;
    if (e < EE) atomicAdd(&g_deg[ei[EE + e]], 1);
}
// scan pass 1: block-local exclusive scan of deg; also computes dinv.
__global__ __launch_bounds__(256) void k_scan1() {
    __shared__ int ws[8];
    int i = blockIdx.x * 256 + threadIdx.x;
    int lane = threadIdx.x & 31, w = threadIdx.x >> 5;
    int v = (i < NN) ? g_deg[i] : 0;
    if (i < NN) g_dinv[i] = rsqrtf((float)v + 1.0f);
    int x = v;
#pragma unroll
    for (int o = 1; o < 32; o <<= 1) {
        int t = __shfl_up_sync(0xffffffffu, x, o);
        if (lane >= o) x += t;
    }
    if (lane == 31) ws[w] = x;
    __syncthreads();
    if (w == 0 && lane < 8) {
        int y = ws[lane];
#pragma unroll
        for (int o = 1; o < 8; o <<= 1) {
            int t = __shfl_up_sync(0xffu, y, o);
            if (lane >= o) y += t;
        }
        ws[lane] = y;
    }
    __syncthreads();
    int base = (w > 0) ? ws[w - 1] : 0;
    if (i < NN) g_off[i] = base + x - v;
    if (threadIdx.x == 255) g_bsum[blockIdx.x] = ws[7];
}
__global__ __launch_bounds__(256) void k_scan2(int nblk) {
    __shared__ int ws[8];
    int lane = threadIdx.x & 31, w = threadIdx.x >> 5;
    int v = (threadIdx.x < nblk) ? g_bsum[threadIdx.x] : 0;
    int x = v;
#pragma unroll
    for (int o = 1; o < 32; o <<= 1) {
        int t = __shfl_up_sync(0xffffffffu, x, o);
        if (lane >= o) x += t;
    }
    if (lane == 31) ws[w] = x;
    __syncthreads();
    if (w == 0 && lane < 8) {
        int y = ws[lane];
#pragma unroll
        for (int o = 1; o < 8; o <<= 1) {
            int t = __shfl_up_sync(0xffu, y, o);
            if (lane >= o) y += t;
        }
        ws[lane] = y;
    }
    __syncthreads();
    int base = (w > 0) ? ws[w - 1] : 0;
    if (threadIdx.x < nblk) g_bsum[threadIdx.x] = base + x - v;
}
__global__ void k_scan3() {
    int i = blockIdx.x * blockDim.x + threadIdx.x;
    if (i < NN) {
        int o = g_off[i] + g_bsum[i >> 8];
        g_off[i] = o;
        g_cur[i] = o;
    }
}
__global__ void k_fill(const int* __restrict__ ei) {
    int e = blockIdx.x * blockDim.x + threadIdx.x;
    if (e < EE) {
        int s = ei[e], d = ei[EE + e];
        int pos = atomicAdd(&g_cur[d], 1);
        g_csr[pos] = s;
    }
}

// ---------------- fused conversions: x (split) + 3 weights (single fp16) ----------------
#define W1SZ (256 * 128)
#define W2SZ (256 * 256)
#define W3SZ (128 * 256)
#define XSZ  (NN * 128)
__global__ void k_cvt_all(const float* __restrict__ x, const float* __restrict__ W1,
                          const float* __restrict__ W2, const float* __restrict__ W3)
{
    int idx = blockIdx.x * blockDim.x + threadIdx.x;
    if (idx < XSZ) {
        int row = idx >> 7, col = idx & 127;
        float v = (col < FIN) ? x[row * FIN + col] : 0.f;
        __half h = __float2half(v);
        g_xA_hi[idx] = h;
        g_xA_lo[idx] = __float2half(v - __half2float(h));
        return;
    }
    int o;
    float v;
    __half* ow;
    if (idx < XSZ + W1SZ) {
        o = idx - XSZ;                      // [N=256][KP=128], K=92
        int n = o >> 7, k = o & 127;
        v = (k < FIN) ? W1[k * DH + n] : 0.f;
        ow = g_w1;
    } else if (idx < XSZ + W1SZ + W2SZ) {
        o = idx - XSZ - W1SZ;               // [N=256][KP=256]
        int n = o >> 8, k = o & 255;
        v = W2[k * DH + n];
        ow = g_w2;
    } else if (idx < XSZ + W1SZ + W2SZ + W3SZ) {
        o = idx - XSZ - W1SZ - W2SZ;        // [N=128][KP=256]
        int n = o >> 8, k = o & 255;
        v = W3[k * DEMB + n];
        ow = g_w3;
    } else return;
    ow[o] = __float2half(v);
}

// ---------------- mma.sync fp16 A-split GEMM (2 MMAs/tile, 48KB smem) ----------------
// C[128 x 128] tile per CTA.  D = Ah*Bh^T + Al*Bh^T, fp32 accum in regs.
// EPI 0: store fp16 C (packed half2).  EPI 1: C = lrelu(C + bias), emit fp16 hi/lo.
#define SM_AH 0
#define SM_AL 16384
#define SM_BH 32768
#define SMEM_BYTES 49152

template <int KP, int EPI>
__global__ __launch_bounds__(256) void k_mma(
    const __half* __restrict__ Ah, const __half* __restrict__ Al,
    const __half* __restrict__ Bh,
    const float* __restrict__ bias, __half* __restrict__ C,
    __half* __restrict__ Ohi, __half* __restrict__ Olo, int Nfull)
{
    extern __shared__ __align__(128) char smem[];
    const uint32_t sb = smem_u32(smem);
    const int tid = threadIdx.x, wid = tid >> 5, lid = tid & 31;
    const int bm = blockIdx.y * 128;
    const int bn = blockIdx.x * 128;
    const int warp_m = wid & 3;   // 4 m-groups of 32 rows
    const int warp_n = wid >> 2;  // 2 n-groups of 64 cols

    float acc[2][8][4];
#pragma unroll
    for (int mt = 0; mt < 2; mt++)
#pragma unroll
        for (int nt = 0; nt < 8; nt++)
#pragma unroll
            for (int q = 0; q < 4; q++) acc[mt][nt][q] = 0.f;

    const int a_r = (lid & 7) + ((lid >> 3) & 1) * 8;
    const int a_u = (lid >> 4) & 1;
    const int b_r = (lid & 7) + ((lid >> 4) & 1) * 8;
    const int b_u = (lid >> 3) & 1;

    constexpr int NKC = KP / 64;
    for (int kc = 0; kc < NKC; kc++) {
        // load 3 tiles of [128 rows x 64 fp16], SW128-swizzled 16B units
#pragma unroll
        for (int i = 0; i < 4; i++) {
            int idx = tid + i * 256;          // 0..1023
            int r = idx >> 3, c16 = idx & 7;
            uint32_t so = (uint32_t)(r * 128 + ((c16 ^ (r & 7)) * 16));
            size_t ga = (size_t)(bm + r) * KP + kc * 64 + c16 * 8;
            size_t gb = (size_t)(bn + r) * KP + kc * 64 + c16 * 8;
            *(uint4*)(smem + SM_AH + so) = *(const uint4*)(Ah + ga);
            *(uint4*)(smem + SM_AL + so) = *(const uint4*)(Al + ga);
            *(uint4*)(smem + SM_BH + so) = *(const uint4*)(Bh + gb);
        }
        __syncthreads();

#pragma unroll
        for (int k16 = 0; k16 < 4; k16++) {
            uint32_t ah[2][4], al[2][4];
#pragma unroll
            for (int mt = 0; mt < 2; mt++) {
                int row = warp_m * 32 + mt * 16 + a_r;
                int u = k16 * 2 + a_u;
                uint32_t off = (uint32_t)(row * 128 + ((u ^ (row & 7)) * 16));
                ldsm_x4(ah[mt][0], ah[mt][1], ah[mt][2], ah[mt][3], sb + SM_AH + off);
                ldsm_x4(al[mt][0], al[mt][1], al[mt][2], al[mt][3], sb + SM_AL + off);
            }
            uint32_t bh[8][2];
#pragma unroll
            for (int g = 0; g < 4; g++) {
                int row = warp_n * 64 + g * 16 + b_r;
                int u = k16 * 2 + b_u;
                uint32_t off = (uint32_t)(row * 128 + ((u ^ (row & 7)) * 16));
                ldsm_x4(bh[2 * g][0], bh[2 * g][1], bh[2 * g + 1][0], bh[2 * g + 1][1],
                        sb + SM_BH + off);
            }
#pragma unroll
            for (int mt = 0; mt < 2; mt++)
#pragma unroll
                for (int nt = 0; nt < 8; nt++) {
                    mma16816(acc[mt][nt], ah[mt], bh[nt]);
                    mma16816(acc[mt][nt], al[mt], bh[nt]);
                }
        }
        __syncthreads();
    }

    // epilogue straight from accumulator fragments
    const int r_base = bm + warp_m * 32 + (lid >> 2);
    const int c_base = bn + warp_n * 64 + (lid & 3) * 2;
#pragma unroll
    for (int mt = 0; mt < 2; mt++) {
#pragma unroll
        for (int h = 0; h < 2; h++) {
            int row = r_base + mt * 16 + h * 8;
            if (row >= NN) continue;
            if (EPI == 0) {
                // packed fp16 store (2 cols per u32)
                uint32_t* cp = (uint32_t*)(C + (size_t)row * Nfull);
#pragma unroll
                for (int nt = 0; nt < 8; nt++)
                    cp[(c_base + nt * 8) >> 1] =
                        pack_f16(acc[mt][nt][2 * h], acc[mt][nt][2 * h + 1]);
            } else {
#pragma unroll
                for (int nt = 0; nt < 8; nt++) {
                    int col = c_base + nt * 8;
                    float v0 = lrelu(acc[mt][nt][2 * h] + bias[col]);
                    float v1 = lrelu(acc[mt][nt][2 * h + 1] + bias[col + 1]);
                    float h0 = __half2float(__float2half(v0));
                    float h1 = __half2float(__float2half(v1));
                    *(uint32_t*)(Ohi + (size_t)row * Nfull + col) = pack_f16(v0, v1);
                    *(uint32_t*)(Olo + (size_t)row * Nfull + col) = pack_f16(v0 - h0, v1 - h1);
                }
            }
        }
    }
}

// ---------------- fused aggregate + bias + LN + lrelu (+L2norm +pool / +fp16 emit) ----------------
// xw is fp16 (uint2 = 4 halves per lane-slot); accumulation in fp32.
template <int D, bool L2NORM, bool POOL, bool EMIT>
__global__ __launch_bounds__(256) void k_agg_ln(
    const __half* __restrict__ xw, const float* __restrict__ bias,
    const float* __restrict__ gam, const float* __restrict__ bet,
    const int* __restrict__ batch, float* __restrict__ out,
    __half* __restrict__ Ohi, __half* __restrict__ Olo)
{
    int row = (blockIdx.x * blockDim.x + threadIdx.x) >> 5;
    int lane = threadIdx.x & 31;
    if (row >= NN) return;
    constexpr int P4 = D / 128;
    const uint2* xw2 = (const uint2*)xw;   // 4 halves per uint2
    float di = g_dinv[row];

    auto ld4 = [&](size_t base, int j) -> float4 {
        uint2 u = xw2[base + lane + 32 * j];
        __half2 p0 = *reinterpret_cast<__half2*>(&u.x);
        __half2 p1 = *reinterpret_cast<__half2*>(&u.y);
        float2 f0 = __half22float2(p0), f1 = __half22float2(p1);
        return make_float4(f0.x, f0.y, f1.x, f1.y);
    };

    float4 acc[P4], acc2[P4];
    {
        float s = di * di;
        size_t rb = (size_t)row * (D / 4);
#pragma unroll
        for (int j = 0; j < P4; j++) {
            float4 v = ld4(rb, j);
            acc[j] = make_float4(v.x * s, v.y * s, v.z * s, v.w * s);
            acc2[j] = make_float4(0.f, 0.f, 0.f, 0.f);
        }
    }
    int o0 = g_off[row];
    int dg = g_deg[row];
    int e = 0;
    for (; e + 2 <= dg; e += 2) {
        int s0 = g_csr[o0 + e];
        int s1 = g_csr[o0 + e + 1];
        float n0 = g_dinv[s0] * di;
        float n1 = g_dinv[s1] * di;
        size_t b0 = (size_t)s0 * (D / 4);
        size_t b1 = (size_t)s1 * (D / 4);
#pragma unroll
        for (int j = 0; j < P4; j++) {
            float4 v0 = ld4(b0, j);
            float4 v1 = ld4(b1, j);
            acc[j].x = fmaf(v0.x, n0, acc[j].x);
            acc[j].y = fmaf(v0.y, n0, acc[j].y);
            acc[j].z = fmaf(v0.z, n0, acc[j].z);
            acc[j].w = fmaf(v0.w, n0, acc[j].w);
            acc2[j].x = fmaf(v1.x, n1, acc2[j].x);
            acc2[j].y = fmaf(v1.y, n1, acc2[j].y);
            acc2[j].z = fmaf(v1.z, n1, acc2[j].z);
            acc2[j].w = fmaf(v1.w, n1, acc2[j].w);
        }
    }
    if (e < dg) {
        int s0 = g_csr[o0 + e];
        float n0 = g_dinv[s0] * di;
        size_t b0 = (size_t)s0 * (D / 4);
#pragma unroll
        for (int j = 0; j < P4; j++) {
            float4 v0 = ld4(b0, j);
            acc[j].x = fmaf(v0.x, n0, acc[j].x);
            acc[j].y = fmaf(v0.y, n0, acc[j].y);
            acc[j].z = fmaf(v0.z, n0, acc[j].z);
            acc[j].w = fmaf(v0.w, n0, acc[j].w);
        }
    }
#pragma unroll
    for (int j = 0; j < P4; j++) {
        acc[j].x += acc2[j].x; acc[j].y += acc2[j].y;
        acc[j].z += acc2[j].z; acc[j].w += acc2[j].w;
    }

    const float4* bias4 = (const float4*)bias;
    float s = 0.f;
#pragma unroll
    for (int j = 0; j < P4; j++) {
        float4 bb = bias4[lane + 32 * j];
        acc[j].x += bb.x; acc[j].y += bb.y; acc[j].z += bb.z; acc[j].w += bb.w;
        s += acc[j].x + acc[j].y + acc[j].z + acc[j].w;
    }
    s = warp_sum(s);
    float mu = s * (1.0f / D);
    float q = 0.f;
#pragma unroll
    for (int j = 0; j < P4; j++) {
        float dx = acc[j].x - mu, dy = acc[j].y - mu;
        float dz = acc[j].z - mu, dw = acc[j].w - mu;
        q += dx * dx + dy * dy + dz * dz + dw * dw;
    }
    q = warp_sum(q);
    float r = rsqrtf(q * (1.0f / D) + EPSLN);

    const float4* gam4 = (const float4*)gam;
    const float4* bet4 = (const float4*)bet;
    float ss = 0.f;
#pragma unroll
    for (int j = 0; j < P4; j++) {
        float4 g = gam4[lane + 32 * j];
        float4 b = bet4[lane + 32 * j];
        float4 y;
        y.x = lrelu((acc[j].x - mu) * r * g.x + b.x);
        y.y = lrelu((acc[j].y - mu) * r * g.y + b.y);
        y.z = lrelu((acc[j].z - mu) * r * g.z + b.z);
        y.w = lrelu((acc[j].w - mu) * r * g.w + b.w);
        acc[j] = y;
        ss += y.x * y.x + y.y * y.y + y.z * y.z + y.w * y.w;
    }
    if (L2NORM) {
        ss = warp_sum(ss);
        float inv = 1.0f / fmaxf(sqrtf(ss), 1e-12f);
#pragma unroll
        for (int j = 0; j < P4; j++) {
            acc[j].x *= inv; acc[j].y *= inv; acc[j].z *= inv; acc[j].w *= inv;
        }
    }
    if (EMIT) {
#pragma unroll
        for (int j = 0; j < P4; j++) {
            float4 y = acc[j];
            float hx = __half2float(__float2half(y.x));
            float hy = __half2float(__float2half(y.y));
            float hz = __half2float(__float2half(y.z));
            float hw = __half2float(__float2half(y.w));
            uint2 vh = make_uint2(pack_f16(y.x, y.y), pack_f16(y.z, y.w));
            uint2 vl = make_uint2(pack_f16(y.x - hx, y.y - hy), pack_f16(y.z - hz, y.w - hw));
            size_t o = (size_t)row * D + 4 * lane + 128 * j;
            *(uint2*)(Ohi + o) = vh;
            *(uint2*)(Olo + o) = vl;
        }
    } else {
        float4* o4 = (float4*)out + (size_t)row * (D / 4);
#pragma unroll
        for (int j = 0; j < P4; j++) o4[lane + 32 * j] = acc[j];
    }
    if (POOL) {
        int b = batch[row];
#pragma unroll
        for (int j = 0; j < P4; j++)
            red_add_v4(g_hg + (size_t)b * DEMB + (4 * lane + 128 * j), acc[j]);
    }
}

// ---------------- final MLP ----------------
__global__ __launch_bounds__(64) void k_mlp(
    const float* __restrict__ W1, const float* __restrict__ b1,
    const float* __restrict__ W2, const float* __restrict__ b2,
    float* __restrict__ out)
{
    int g = blockIdx.x;
    int t = threadIdx.x;
    __shared__ float sh[DEMB];
    __shared__ float red[2];
    sh[t] = g_hg[(size_t)g * DEMB + t];
    sh[t + 64] = g_hg[(size_t)g * DEMB + 64 + t];
    __syncthreads();
    float s = b1[t];
#pragma unroll
    for (int k = 0; k < DEMB; k++) s = fmaf(sh[k], W1[k * 64 + t], s);
    s = lrelu(s);
    s *= W2[t];
    s = warp_sum(s);
    if ((t & 31) == 0) red[t >> 5] = s;
    __syncthreads();
    if (t == 0) out[g] = red[0] + red[1] + b2[0];
}

// ---------------- launch ----------------
extern "C" void kernel_launch(void* const* d_in, const int* in_sizes, int n_in,
                              void* d_out, int out_size)
{
    const float* x     = (const float*)d_in[0];
    const int*   ei    = (const int*)  d_in[1];
    const int*   batch = (const int*)  d_in[2];
    const float* nfcW  = (const float*)d_in[3];
    const float* nfcb  = (const float*)d_in[4];
    const float* gn1g  = (const float*)d_in[5];
    const float* gn1b  = (const float*)d_in[6];
    const float* gc1W  = (const float*)d_in[7];
    const float* gc1b  = (const float*)d_in[8];
    const float* gn2g  = (const float*)d_in[9];
    const float* gn2b  = (const float*)d_in[10];
    const float* gc2W  = (const float*)d_in[11];
    const float* gc2b  = (const float*)d_in[12];
    const float* fc1W  = (const float*)d_in[13];
    const float* fc1b  = (const float*)d_in[14];
    const float* fc2W  = (const float*)d_in[15];
    const float* fc2b  = (const float*)d_in[16];

    float* out   = (float*)d_out;
    float* outHa = out + GGR;

    __half* xw;  cudaGetSymbolAddress((void**)&xw, g_xw);
    __half *xAh, *xAl, *h1h, *h1l, *h2h, *h2l, *w1, *w2, *w3;
    cudaGetSymbolAddress((void**)&xAh, g_xA_hi); cudaGetSymbolAddress((void**)&xAl, g_xA_lo);
    cudaGetSymbolAddress((void**)&h1h, g_h1_hi); cudaGetSymbolAddress((void**)&h1l, g_h1_lo);
    cudaGetSymbolAddress((void**)&h2h, g_h2_hi); cudaGetSymbolAddress((void**)&h2l, g_h2_lo);
    cudaGetSymbolAddress((void**)&w1, g_w1);
    cudaGetSymbolAddress((void**)&w2, g_w2);
    cudaGetSymbolAddress((void**)&w3, g_w3);

    cudaFuncSetAttribute(k_mma<128, 1>, cudaFuncAttributeMaxDynamicSharedMemorySize, SMEM_BYTES);
    cudaFuncSetAttribute(k_mma<256, 0>, cudaFuncAttributeMaxDynamicSharedMemorySize, SMEM_BYTES);

    const int NB = (NN + 255) / 256;
    const int MBLK = NNP / 128;  // 391

    // 1) degree + dinv + CSR build
    k_zero<<<(GGR * DEMB + 255) / 256, 256>>>();
    k_deg_count<<<(EE + 255) / 256, 256>>>(ei);
    k_scan1<<<NB, 256>>>();
    k_scan2<<<1, 256>>>(NB);
    k_scan3<<<NB, 256>>>();
    k_fill<<<(EE + 255) / 256, 256>>>(ei);

    // 2) fused operand conversions (x split + 3 weights single fp16)
    k_cvt_all<<<(XSZ + W1SZ + W2SZ + W3SZ + 255) / 256, 256>>>(x, nfcW, gc1W, gc2W);

    // 3) encoder: h1 = lrelu(x @ nfcW + b) -> fp16 hi/lo
    k_mma<128, 1><<<dim3(2, MBLK), 256, SMEM_BYTES>>>(
        xAh, xAl, w1, nfcb, nullptr, h1h, h1l, DH);

    // 4) conv1: xw = h1 @ gc1W (fp16) ; agg+LN+lrelu -> h2 fp16 hi/lo
    k_mma<256, 0><<<dim3(2, MBLK), 256, SMEM_BYTES>>>(
        h1h, h1l, w2, nullptr, xw, nullptr, nullptr, DH);
    k_agg_ln<DH, false, false, true><<<(NN * 32 + 255) / 256, 256>>>(
        xw, gc1b, gn1g, gn1b, batch, nullptr, h2h, h2l);

    // 5) conv2: xw = h2 @ gc2W (fp16) ; agg+LN+lrelu+L2norm+pool -> outHa
    k_mma<256, 0><<<dim3(1, MBLK), 256, SMEM_BYTES>>>(
        h2h, h2l, w3, nullptr, xw, nullptr, nullptr, DEMB);
    k_agg_ln<DEMB, true, true, false><<<(NN * 32 + 255) / 256, 256>>>(
        xw, gc2b, gn2g, gn2b, batch, outHa, nullptr, nullptr);

    // 6) MLP head
    k_mlp<<<GGR, 64>>>(fc1W, fc1b, fc2W, fc2b, out);
}

// round 14
// speedup vs baseline: 2.0658x; 1.4121x over previous
#include <cuda_runtime.h>
#include <cuda_fp16.h>
#include <math.h>
#include <stdint.h>

#define NN   50000
#define NNP  50048              // padded to multiple of 128
#define EE   400000
#define GGR  500
#define FIN  92
#define DH   256
#define DEMB 128
#define EPSLN 1e-5f

// ---------------- scratch (no allocations allowed) ----------------
__device__ __half g_xw[NN * DH];           // GEMM output (pre-aggregation), fp16
__device__ float g_dinv[NN];
__device__ int   g_deg[NN];
__device__ int   g_off[NN];
__device__ int   g_cur[NN];
__device__ int   g_csr[EE];
__device__ int   g_bsum[256];
__device__ float g_hg[GGR * DEMB];

// fp16 operand buffers (plain fp16, no hi/lo split)
__device__ __half g_xA[NNP * 128];
__device__ __half g_h1[NNP * 256];
__device__ __half g_h2[NNP * 256];
__device__ __half g_w1[256 * 128];   // nfcW^T padded [N=256][KP=128]
__device__ __half g_w2[256 * 256];   // gc1W^T
__device__ __half g_w3[128 * 256];   // gc2W^T

// ---------------- small helpers ----------------
__device__ __forceinline__ float warp_sum(float v) {
#pragma unroll
    for (int o = 16; o > 0; o >>= 1) v += __shfl_xor_sync(0xffffffffu, v, o);
    return v;
}
__device__ __forceinline__ float lrelu(float v) { return v > 0.f ? v : 0.01f * v; }

__device__ __forceinline__ void red_add_v4(float* p, float4 v) {
    asm volatile("red.global.add.v4.f32 [%0], {%1, %2, %3, %4};"
                 :: "l"(p), "f"(v.x), "f"(v.y), "f"(v.z), "f"(v.w) : "memory");
}
__device__ __forceinline__ uint32_t pack_f16(float a, float b) {
    __half2 t = __halves2half2(__float2half(a), __float2half(b));
    return *reinterpret_cast<uint32_t*>(&t);
}
__device__ __forceinline__ uint32_t smem_u32(const void* p) {
    return (uint32_t)__cvta_generic_to_shared(p);
}
__device__ __forceinline__ void ldsm_x4(uint32_t& r0, uint32_t& r1, uint32_t& r2,
                                        uint32_t& r3, uint32_t addr) {
    asm volatile("ldmatrix.sync.aligned.m8n8.x4.shared.b16 {%0,%1,%2,%3}, [%4];"
                 : "=r"(r0), "=r"(r1), "=r"(r2), "=r"(r3) : "r"(addr));
}
__device__ __forceinline__ void mma16816(float* d, const uint32_t* a, const uint32_t* b) {
    asm volatile(
        "mma.sync.aligned.m16n8k16.row.col.f32.f16.f16.f32 "
        "{%0,%1,%2,%3}, {%4,%5,%6,%7}, {%8,%9}, {%0,%1,%2,%3};"
        : "+f"(d[0]), "+f"(d[1]), "+f"(d[2]), "+f"(d[3])
        : "r"(a[0]), "r"(a[1]), "r"(a[2]), "r"(a[3]), "r"(b[0]), "r"(b[1]));
}

// ---------------- degree / zero / CSR ----------------
__global__ void k_zero() {
    int i = blockIdx.x * blockDim.x + threadIdx.x;
    if (i < NN) g_deg[i] = 0;
    if (i < GGR * DEMB) g_hg[i] = 0.f;
}
__global__ void k_deg_count(const int* __restrict__ ei) {
    int e = blockIdx.x * blockDim.x + threadIdx.x;
    if (e < EE) atomicAdd(&g_deg[ei[EE + e]], 1);
}
// scan pass 1: block-local exclusive scan of deg; also computes dinv.
__global__ __launch_bounds__(256) void k_scan1() {
    __shared__ int ws[8];
    int i = blockIdx.x * 256 + threadIdx.x;
    int lane = threadIdx.x & 31, w = threadIdx.x >> 5;
    int v = (i < NN) ? g_deg[i] : 0;
    if (i < NN) g_dinv[i] = rsqrtf((float)v + 1.0f);
    int x = v;
#pragma unroll
    for (int o = 1; o < 32; o <<= 1) {
        int t = __shfl_up_sync(0xffffffffu, x, o);
        if (lane >= o) x += t;
    }
    if (lane == 31) ws[w] = x;
    __syncthreads();
    if (w == 0 && lane < 8) {
        int y = ws[lane];
#pragma unroll
        for (int o = 1; o < 8; o <<= 1) {
            int t = __shfl_up_sync(0xffu, y, o);
            if (lane >= o) y += t;
        }
        ws[lane] = y;
    }
    __syncthreads();
    int base = (w > 0) ? ws[w - 1] : 0;
    if (i < NN) g_off[i] = base + x - v;
    if (threadIdx.x == 255) g_bsum[blockIdx.x] = ws[7];
}
__global__ __launch_bounds__(256) void k_scan2(int nblk) {
    __shared__ int ws[8];
    int lane = threadIdx.x & 31, w = threadIdx.x >> 5;
    int v = (threadIdx.x < nblk) ? g_bsum[threadIdx.x] : 0;
    int x = v;
#pragma unroll
    for (int o = 1; o < 32; o <<= 1) {
        int t = __shfl_up_sync(0xffffffffu, x, o);
        if (lane >= o) x += t;
    }
    if (lane == 31) ws[w] = x;
    __syncthreads();
    if (w == 0 && lane < 8) {
        int y = ws[lane];
#pragma unroll
        for (int o = 1; o < 8; o <<= 1) {
            int t = __shfl_up_sync(0xffu, y, o);
            if (lane >= o) y += t;
        }
        ws[lane] = y;
    }
    __syncthreads();
    int base = (w > 0) ? ws[w - 1] : 0;
    if (threadIdx.x < nblk) g_bsum[threadIdx.x] = base + x - v;
}
__global__ void k_scan3() {
    int i = blockIdx.x * blockDim.x + threadIdx.x;
    if (i < NN) {
        int o = g_off[i] + g_bsum[i >> 8];
        g_off[i] = o;
        g_cur[i] = o;
    }
}
__global__ void k_fill(const int* __restrict__ ei) {
    int e = blockIdx.x * blockDim.x + threadIdx.x;
    if (e < EE) {
        int s = ei[e], d = ei[EE + e];
        int pos = atomicAdd(&g_cur[d], 1);
        g_csr[pos] = s;
    }
}

// ---------------- fused conversions: x + 3 weights, single fp16 ----------------
#define W1SZ (256 * 128)
#define W2SZ (256 * 256)
#define W3SZ (128 * 256)
#define XSZ  (NN * 128)
__global__ void k_cvt_all(const float* __restrict__ x, const float* __restrict__ W1,
                          const float* __restrict__ W2, const float* __restrict__ W3)
{
    int idx = blockIdx.x * blockDim.x + threadIdx.x;
    int o;
    float v;
    __half* ow;
    if (idx < XSZ) {
        int row = idx >> 7, col = idx & 127;
        v = (col < FIN) ? x[row * FIN + col] : 0.f;
        ow = g_xA; o = idx;
    } else if (idx < XSZ + W1SZ) {
        o = idx - XSZ;                      // [N=256][KP=128], K=92
        int n = o >> 7, k = o & 127;
        v = (k < FIN) ? W1[k * DH + n] : 0.f;
        ow = g_w1;
    } else if (idx < XSZ + W1SZ + W2SZ) {
        o = idx - XSZ - W1SZ;               // [N=256][KP=256]
        int n = o >> 8, k = o & 255;
        v = W2[k * DH + n];
        ow = g_w2;
    } else if (idx < XSZ + W1SZ + W2SZ + W3SZ) {
        o = idx - XSZ - W1SZ - W2SZ;        // [N=128][KP=256]
        int n = o >> 8, k = o & 255;
        v = W3[k * DEMB + n];
        ow = g_w3;
    } else return;
    ow[o] = __float2half(v);
}

// ---------------- mma.sync fp16 GEMM (1 MMA/tile, 32KB smem) ----------------
// C[128 x 128] tile per CTA.  D = A*B^T, fp32 accum in regs.
// EPI 0: store fp16 C (packed half2).  EPI 1: C = lrelu(C + bias), emit fp16.
#define SM_A 0
#define SM_B 16384
#define SMEM_BYTES 32768

template <int KP, int EPI>
__global__ __launch_bounds__(256) void k_mma(
    const __half* __restrict__ A, const __half* __restrict__ B,
    const float* __restrict__ bias, __half* __restrict__ C,
    __half* __restrict__ O, int Nfull)
{
    extern __shared__ __align__(128) char smem[];
    const uint32_t sb = smem_u32(smem);
    const int tid = threadIdx.x, wid = tid >> 5, lid = tid & 31;
    const int bm = blockIdx.y * 128;
    const int bn = blockIdx.x * 128;
    const int warp_m = wid & 3;   // 4 m-groups of 32 rows
    const int warp_n = wid >> 2;  // 2 n-groups of 64 cols

    float acc[2][8][4];
#pragma unroll
    for (int mt = 0; mt < 2; mt++)
#pragma unroll
        for (int nt = 0; nt < 8; nt++)
#pragma unroll
            for (int q = 0; q < 4; q++) acc[mt][nt][q] = 0.f;

    const int a_r = (lid & 7) + ((lid >> 3) & 1) * 8;
    const int a_u = (lid >> 4) & 1;
    const int b_r = (lid & 7) + ((lid >> 4) & 1) * 8;
    const int b_u = (lid >> 3) & 1;

    constexpr int NKC = KP / 64;
    for (int kc = 0; kc < NKC; kc++) {
        // load 2 tiles of [128 rows x 64 fp16], SW128-swizzled 16B units
#pragma unroll
        for (int i = 0; i < 4; i++) {
            int idx = tid + i * 256;          // 0..1023
            int r = idx >> 3, c16 = idx & 7;
            uint32_t so = (uint32_t)(r * 128 + ((c16 ^ (r & 7)) * 16));
            size_t ga = (size_t)(bm + r) * KP + kc * 64 + c16 * 8;
            size_t gb = (size_t)(bn + r) * KP + kc * 64 + c16 * 8;
            *(uint4*)(smem + SM_A + so) = *(const uint4*)(A + ga);
            *(uint4*)(smem + SM_B + so) = *(const uint4*)(B + gb);
        }
        __syncthreads();

#pragma unroll
        for (int k16 = 0; k16 < 4; k16++) {
            uint32_t ah[2][4];
#pragma unroll
            for (int mt = 0; mt < 2; mt++) {
                int row = warp_m * 32 + mt * 16 + a_r;
                int u = k16 * 2 + a_u;
                uint32_t off = (uint32_t)(row * 128 + ((u ^ (row & 7)) * 16));
                ldsm_x4(ah[mt][0], ah[mt][1], ah[mt][2], ah[mt][3], sb + SM_A + off);
            }
            uint32_t bh[8][2];
#pragma unroll
            for (int g = 0; g < 4; g++) {
                int row = warp_n * 64 + g * 16 + b_r;
                int u = k16 * 2 + b_u;
                uint32_t off = (uint32_t)(row * 128 + ((u ^ (row & 7)) * 16));
                ldsm_x4(bh[2 * g][0], bh[2 * g][1], bh[2 * g + 1][0], bh[2 * g + 1][1],
                        sb + SM_B + off);
            }
#pragma unroll
            for (int mt = 0; mt < 2; mt++)
#pragma unroll
                for (int nt = 0; nt < 8; nt++)
                    mma16816(acc[mt][nt], ah[mt], bh[nt]);
        }
        __syncthreads();
    }

    // epilogue straight from accumulator fragments
    const int r_base = bm + warp_m * 32 + (lid >> 2);
    const int c_base = bn + warp_n * 64 + (lid & 3) * 2;
#pragma unroll
    for (int mt = 0; mt < 2; mt++) {
#pragma unroll
        for (int h = 0; h < 2; h++) {
            int row = r_base + mt * 16 + h * 8;
            if (row >= NN) continue;
            if (EPI == 0) {
                uint32_t* cp = (uint32_t*)(C + (size_t)row * Nfull);
#pragma unroll
                for (int nt = 0; nt < 8; nt++)
                    cp[(c_base + nt * 8) >> 1] =
                        pack_f16(acc[mt][nt][2 * h], acc[mt][nt][2 * h + 1]);
            } else {
                uint32_t* op = (uint32_t*)(O + (size_t)row * Nfull);
#pragma unroll
                for (int nt = 0; nt < 8; nt++) {
                    int col = c_base + nt * 8;
                    float v0 = lrelu(acc[mt][nt][2 * h] + bias[col]);
                    float v1 = lrelu(acc[mt][nt][2 * h + 1] + bias[col + 1]);
                    op[col >> 1] = pack_f16(v0, v1);
                }
            }
        }
    }
}

// ---------------- fused aggregate + bias + LN + lrelu (+L2norm +pool / +fp16 emit) ----------------
// xw is fp16 (uint2 = 4 halves per lane-slot); accumulation in fp32.
template <int D, bool L2NORM, bool POOL, bool EMIT>
__global__ __launch_bounds__(256) void k_agg_ln(
    const __half* __restrict__ xw, const float* __restrict__ bias,
    const float* __restrict__ gam, const float* __restrict__ bet,
    const int* __restrict__ batch, float* __restrict__ out,
    __half* __restrict__ Oh)
{
    int row = (blockIdx.x * blockDim.x + threadIdx.x) >> 5;
    int lane = threadIdx.x & 31;
    if (row >= NN) return;
    constexpr int P4 = D / 128;
    const uint2* xw2 = (const uint2*)xw;   // 4 halves per uint2
    float di = g_dinv[row];

    auto ld4 = [&](size_t base, int j) -> float4 {
        uint2 u = xw2[base + lane + 32 * j];
        __half2 p0 = *reinterpret_cast<__half2*>(&u.x);
        __half2 p1 = *reinterpret_cast<__half2*>(&u.y);
        float2 f0 = __half22float2(p0), f1 = __half22float2(p1);
        return make_float4(f0.x, f0.y, f1.x, f1.y);
    };

    float4 acc[P4], acc2[P4];
    {
        float s = di * di;
        size_t rb = (size_t)row * (D / 4);
#pragma unroll
        for (int j = 0; j < P4; j++) {
            float4 v = ld4(rb, j);
            acc[j] = make_float4(v.x * s, v.y * s, v.z * s, v.w * s);
            acc2[j] = make_float4(0.f, 0.f, 0.f, 0.f);
        }
    }
    int o0 = g_off[row];
    int dg = g_deg[row];
    int e = 0;
    for (; e + 2 <= dg; e += 2) {
        int s0 = g_csr[o0 + e];
        int s1 = g_csr[o0 + e + 1];
        float n0 = g_dinv[s0] * di;
        float n1 = g_dinv[s1] * di;
        size_t b0 = (size_t)s0 * (D / 4);
        size_t b1 = (size_t)s1 * (D / 4);
#pragma unroll
        for (int j = 0; j < P4; j++) {
            float4 v0 = ld4(b0, j);
            float4 v1 = ld4(b1, j);
            acc[j].x = fmaf(v0.x, n0, acc[j].x);
            acc[j].y = fmaf(v0.y, n0, acc[j].y);
            acc[j].z = fmaf(v0.z, n0, acc[j].z);
            acc[j].w = fmaf(v0.w, n0, acc[j].w);
            acc2[j].x = fmaf(v1.x, n1, acc2[j].x);
            acc2[j].y = fmaf(v1.y, n1, acc2[j].y);
            acc2[j].z = fmaf(v1.z, n1, acc2[j].z);
            acc2[j].w = fmaf(v1.w, n1, acc2[j].w);
        }
    }
    if (e < dg) {
        int s0 = g_csr[o0 + e];
        float n0 = g_dinv[s0] * di;
        size_t b0 = (size_t)s0 * (D / 4);
#pragma unroll
        for (int j = 0; j < P4; j++) {
            float4 v0 = ld4(b0, j);
            acc[j].x = fmaf(v0.x, n0, acc[j].x);
            acc[j].y = fmaf(v0.y, n0, acc[j].y);
            acc[j].z = fmaf(v0.z, n0, acc[j].z);
            acc[j].w = fmaf(v0.w, n0, acc[j].w);
        }
    }
#pragma unroll
    for (int j = 0; j < P4; j++) {
        acc[j].x += acc2[j].x; acc[j].y += acc2[j].y;
        acc[j].z += acc2[j].z; acc[j].w += acc2[j].w;
    }

    const float4* bias4 = (const float4*)bias;
    float s = 0.f;
#pragma unroll
    for (int j = 0; j < P4; j++) {
        float4 bb = bias4[lane + 32 * j];
        acc[j].x += bb.x; acc[j].y += bb.y; acc[j].z += bb.z; acc[j].w += bb.w;
        s += acc[j].x + acc[j].y + acc[j].z + acc[j].w;
    }
    s = warp_sum(s);
    float mu = s * (1.0f / D);
    float q = 0.f;
#pragma unroll
    for (int j = 0; j < P4; j++) {
        float dx = acc[j].x - mu, dy = acc[j].y - mu;
        float dz = acc[j].z - mu, dw = acc[j].w - mu;
        q += dx * dx + dy * dy + dz * dz + dw * dw;
    }
    q = warp_sum(q);
    float r = rsqrtf(q * (1.0f / D) + EPSLN);

    const float4* gam4 = (const float4*)gam;
    const float4* bet4 = (const float4*)bet;
    float ss = 0.f;
#pragma unroll
    for (int j = 0; j < P4; j++) {
        float4 g = gam4[lane + 32 * j];
        float4 b = bet4[lane + 32 * j];
        float4 y;
        y.x = lrelu((acc[j].x - mu) * r * g.x + b.x);
        y.y = lrelu((acc[j].y - mu) * r * g.y + b.y);
        y.z = lrelu((acc[j].z - mu) * r * g.z + b.z);
        y.w = lrelu((acc[j].w - mu) * r * g.w + b.w);
        acc[j] = y;
        ss += y.x * y.x + y.y * y.y + y.z * y.z + y.w * y.w;
    }
    if (L2NORM) {
        ss = warp_sum(ss);
        float inv = 1.0f / fmaxf(sqrtf(ss), 1e-12f);
#pragma unroll
        for (int j = 0; j < P4; j++) {
            acc[j].x *= inv; acc[j].y *= inv; acc[j].z *= inv; acc[j].w *= inv;
        }
    }
    if (EMIT) {
#pragma unroll
        for (int j = 0; j < P4; j++) {
            float4 y = acc[j];
            uint2 vh = make_uint2(pack_f16(y.x, y.y), pack_f16(y.z, y.w));
            size_t o = (size_t)row * D + 4 * lane + 128 * j;
            *(uint2*)(Oh + o) = vh;
        }
    } else {
        float4* o4 = (float4*)out + (size_t)row * (D / 4);
#pragma unroll
        for (int j = 0; j < P4; j++) o4[lane + 32 * j] = acc[j];
    }
    if (POOL) {
        int b = batch[row];
#pragma unroll
        for (int j = 0; j < P4; j++)
            red_add_v4(g_hg + (size_t)b * DEMB + (4 * lane + 128 * j), acc[j]);
    }
}

// ---------------- final MLP ----------------
__global__ __launch_bounds__(64) void k_mlp(
    const float* __restrict__ W1, const float* __restrict__ b1,
    const float* __restrict__ W2, const float* __restrict__ b2,
    float* __restrict__ out)
{
    int g = blockIdx.x;
    int t = threadIdx.x;
    __shared__ float sh[DEMB];
    __shared__ float red[2];
    sh[t] = g_hg[(size_t)g * DEMB + t];
    sh[t + 64] = g_hg[(size_t)g * DEMB + 64 + t];
    __syncthreads();
    float s = b1[t];
#pragma unroll
    for (int k = 0; k < DEMB; k++) s = fmaf(sh[k], W1[k * 64 + t], s);
    s = lrelu(s);
    s *= W2[t];
    s = warp_sum(s);
    if ((t & 31) == 0) red[t >> 5] = s;
    __syncthreads();
    if (t == 0) out[g] = red[0] + red[1] + b2[0];
}

// ---------------- launch ----------------
extern "C" void kernel_launch(void* const* d_in, const int* in_sizes, int n_in,
                              void* d_out, int out_size)
{
    const float* x     = (const float*)d_in[0];
    const int*   ei    = (const int*)  d_in[1];
    const int*   batch = (const int*)  d_in[2];
    const float* nfcW  = (const float*)d_in[3];
    const float* nfcb  = (const float*)d_in[4];
    const float* gn1g  = (const float*)d_in[5];
    const float* gn1b  = (const float*)d_in[6];
    const float* gc1W  = (const float*)d_in[7];
    const float* gc1b  = (const float*)d_in[8];
    const float* gn2g  = (const float*)d_in[9];
    const float* gn2b  = (const float*)d_in[10];
    const float* gc2W  = (const float*)d_in[11];
    const float* gc2b  = (const float*)d_in[12];
    const float* fc1W  = (const float*)d_in[13];
    const float* fc1b  = (const float*)d_in[14];
    const float* fc2W  = (const float*)d_in[15];
    const float* fc2b  = (const float*)d_in[16];

    float* out   = (float*)d_out;
    float* outHa = out + GGR;

    __half* xw;  cudaGetSymbolAddress((void**)&xw, g_xw);
    __half *xA, *h1, *h2, *w1, *w2, *w3;
    cudaGetSymbolAddress((void**)&xA, g_xA);
    cudaGetSymbolAddress((void**)&h1, g_h1);
    cudaGetSymbolAddress((void**)&h2, g_h2);
    cudaGetSymbolAddress((void**)&w1, g_w1);
    cudaGetSymbolAddress((void**)&w2, g_w2);
    cudaGetSymbolAddress((void**)&w3, g_w3);

    cudaFuncSetAttribute(k_mma<128, 1>, cudaFuncAttributeMaxDynamicSharedMemorySize, SMEM_BYTES);
    cudaFuncSetAttribute(k_mma<256, 0>, cudaFuncAttributeMaxDynamicSharedMemorySize, SMEM_BYTES);

    const int NB = (NN + 255) / 256;
    const int MBLK = NNP / 128;  // 391

    // 1) degree + dinv + CSR build
    k_zero<<<(GGR * DEMB + 255) / 256, 256>>>();
    k_deg_count<<<(EE + 255) / 256, 256>>>(ei);
    k_scan1<<<NB, 256>>>();
    k_scan2<<<1, 256>>>(NB);
    k_scan3<<<NB, 256>>>();
    k_fill<<<(EE + 255) / 256, 256>>>(ei);

    // 2) fused operand conversions (x + 3 weights, single fp16)
    k_cvt_all<<<(XSZ + W1SZ + W2SZ + W3SZ + 255) / 256, 256>>>(x, nfcW, gc1W, gc2W);

    // 3) encoder: h1 = lrelu(x @ nfcW + b) -> fp16
    k_mma<128, 1><<<dim3(2, MBLK), 256, SMEM_BYTES>>>(xA, w1, nfcb, nullptr, h1, DH);

    // 4) conv1: xw = h1 @ gc1W (fp16) ; agg+LN+lrelu -> h2 fp16
    k_mma<256, 0><<<dim3(2, MBLK), 256, SMEM_BYTES>>>(h1, w2, nullptr, xw, nullptr, DH);
    k_agg_ln<DH, false, false, true><<<(NN * 32 + 255) / 256, 256>>>(
        xw, gc1b, gn1g, gn1b, batch, nullptr, h2);

    // 5) conv2: xw = h2 @ gc2W (fp16) ; agg+LN+lrelu+L2norm+pool -> outHa
    k_mma<256, 0><<<dim3(1, MBLK), 256, SMEM_BYTES>>>(h2, w3, nullptr, xw, nullptr, DEMB);
    k_agg_ln<DEMB, true, true, false><<<(NN * 32 + 255) / 256, 256>>>(
        xw, gc2b, gn2g, gn2b, batch, outHa, nullptr);

    // 6) MLP head
    k_mlp<<<GGR, 64>>>(fc1W, fc1b, fc2W, fc2b, out);
}